// round 1
// baseline (speedup 1.0000x reference)
#include <cuda_runtime.h>
#include <math.h>

#define T 8192
#define D 1024
#define DCND 256
#define NE 8
#define HID 4096
#define CAP 2560
#define NTOK (T*2)           // 16384 (token,k) pairs
#define ROWS_R (NE*CAP)      // 20480 routed slots
#define ROWS_ALL (ROWS_R+T)  // 28672 unified rows (routed + shared)
#define AD3 3072
#define NCHUNK 64
#define CHUNK 256

// ---------------- scratch (device globals; no allocations) ----------------
__device__ int   g_tope[NTOK];
__device__ float g_topw[NTOK];
__device__ int   g_hist[NCHUNK*NE];
__device__ int   g_coff[NCHUNK*NE];
__device__ int   g_tpe[NE];
__device__ int   g_starts[NE];
__device__ int   g_ne[NE];
__device__ int   g_slot_tok[ROWS_R];
__device__ float g_slot_w[ROWS_R];
__device__ float g_mu[T];
__device__ float g_rstd[T];
__device__ float g_ada[(size_t)ROWS_ALL*AD3];   // shift|scale|gate
__device__ float g_h[(size_t)ROWS_ALL*D];       // modulated LN input
__device__ float g_u[(size_t)ROWS_ALL*HID];     // gelu(h@W1+b1)
__device__ float g_moe[(size_t)T*D];
__device__ float g_sy[(size_t)T*D];

struct P {
  const float *x,*cond,*mask;
  const float *Wada_s,*bada_s,*W1_s,*b1_s,*W2_s,*b2_s;
  const float *Wada_e,*bada_e,*W1_e,*b1_e,*W2_e,*b2_e;
};

// ---------------- router: warp/token, top-2 of 7 ----------------
__global__ void k_router(const float* __restrict__ x, const float* __restrict__ Wg){
  int w=(blockIdx.x*blockDim.x+threadIdx.x)>>5;
  int lane=threadIdx.x&31;
  if(w>=T) return;
  const float* xr=x+(size_t)w*D;
  float a[7]={0.f,0.f,0.f,0.f,0.f,0.f,0.f};
  for(int k=lane;k<D;k+=32){
    float xv=xr[k];
    #pragma unroll
    for(int j=0;j<7;j++) a[j]+=xv*Wg[k*7+j];
  }
  #pragma unroll
  for(int j=0;j<7;j++)
    for(int o=16;o;o>>=1) a[j]+=__shfl_xor_sync(0xffffffffu,a[j],o);
  if(lane==0){
    int j0=0;
    #pragma unroll
    for(int j=1;j<7;j++) if(a[j]>a[j0]) j0=j;   // first max (stable)
    int j1=-1;
    #pragma unroll
    for(int j=0;j<7;j++){ if(j==j0) continue; if(j1<0||a[j]>a[j1]) j1=j; }
    float e1=expf(a[j1]-a[j0]);
    float inv=1.f/(1.f+e1);            // normalized top-2 softmax weights
    g_tope[2*w]=j0;   g_topw[2*w]=inv;
    g_tope[2*w+1]=j1; g_topw[2*w+1]=e1*inv;
  }
}

// ---------------- stable counting sort by expert ----------------
__global__ void k_hist(){
  __shared__ int cnt[NE];
  int tid=threadIdx.x;
  if(tid<NE) cnt[tid]=0;
  __syncthreads();
  atomicAdd(&cnt[g_tope[blockIdx.x*CHUNK+tid]],1);
  __syncthreads();
  if(tid<NE) g_hist[blockIdx.x*NE+tid]=cnt[tid];
}

__global__ void k_scan(){
  int tid=threadIdx.x;
  __shared__ int tpe[NE], st[NE];
  if(tid<NE){
    int s=0;
    for(int c=0;c<NCHUNK;c++) s+=g_hist[c*NE+tid];
    tpe[tid]=s; g_tpe[tid]=s; g_ne[tid]=s<CAP?s:CAP;
  }
  __syncthreads();
  if(tid==0){
    int cum=0;
    for(int e=0;e<NE;e++){ st[e]=cum; g_starts[e]=cum; cum+=tpe[e]; }
  }
  __syncthreads();
  if(tid<NE){
    int run=st[tid];
    for(int c=0;c<NCHUNK;c++){ g_coff[c*NE+tid]=run; run+=g_hist[c*NE+tid]; }
  }
}

__global__ void k_place(){
  __shared__ int se[CHUNK];
  int tid=threadIdx.x;
  int g=blockIdx.x*CHUNK+tid;
  int e=g_tope[g];
  se[tid]=e;
  __syncthreads();
  int rank=0;
  for(int j=0;j<tid;j++) rank += (se[j]==e);
  int pos=g_coff[blockIdx.x*NE+e]+rank;
  int slot=pos-g_starts[e];
  if(slot<CAP){
    g_slot_tok[e*CAP+slot]=g>>1;
    g_slot_w[e*CAP+slot]=g_topw[g];
  }
}

// ---------------- LN stats: warp/token ----------------
__global__ void k_lnstats(const float* __restrict__ x){
  int w=(blockIdx.x*blockDim.x+threadIdx.x)>>5;
  int lane=threadIdx.x&31;
  if(w>=T) return;
  const float* xr=x+(size_t)w*D;
  float s=0.f,s2=0.f;
  for(int k=lane;k<D;k+=32){ float v=xr[k]; s+=v; s2+=v*v; }
  for(int o=16;o;o>>=1){
    s+=__shfl_xor_sync(0xffffffffu,s,o);
    s2+=__shfl_xor_sync(0xffffffffu,s2,o);
  }
  if(lane==0){
    float mu=s*(1.f/(float)D);
    float var=s2*(1.f/(float)D)-mu*mu;
    g_mu[w]=mu;
    g_rstd[w]=rsqrtf(var+1e-5f);
  }
}

// ---------------- modulate: h = LN(x)*(1+scale)+shift ----------------
__global__ void k_mod(const float* __restrict__ x){
  int r=blockIdx.x;
  int tok=(r<ROWS_R)? g_slot_tok[r] : (r-ROWS_R);
  int d4=threadIdx.x;                       // 0..255, one float4 each
  float4* hp=(float4*)(g_h+(size_t)r*D);
  if(tok<0){ hp[d4]=make_float4(0.f,0.f,0.f,0.f); return; }
  const float4* xp=(const float4*)(x+(size_t)tok*D);
  float mu=g_mu[tok], rs=g_rstd[tok];
  const float* ada=g_ada+(size_t)r*AD3;
  float4 xv=xp[d4];
  float4 sh=((const float4*)ada)[d4];
  float4 sc=((const float4*)(ada+D))[d4];
  float4 h;
  h.x=(xv.x-mu)*rs*(1.f+sc.x)+sh.x;
  h.y=(xv.y-mu)*rs*(1.f+sc.y)+sh.y;
  h.z=(xv.z-mu)*rs*(1.f+sc.z)+sh.z;
  h.w=(xv.w-mu)*rs*(1.f+sc.w)+sh.w;
  hp[d4]=h;
}

__device__ __forceinline__ float gelu_tanh(float v){
  const float c=0.7978845608028654f;
  return 0.5f*v*(1.f+tanhf(c*(v+0.044715f*v*v*v)));
}

// ---------------- generic 128x128x8 fp32 GEMM, per-expert grid.z ----------------
// MODE 0: ada = gather(cond) @ Wada + bada              (K=256,  N=3072)
// MODE 1: u   = gelu(h @ W1 + b1)                       (K=1024, N=4096)
// MODE 2: y   = u @ W2 + b2 -> gate*mask*w scatter      (K=4096, N=1024)
template<int MODE>
__global__ void __launch_bounds__(256) k_gemm(P p){
  constexpr int KD=(MODE==0)?DCND:(MODE==1)?D:HID;
  constexpr int ND=(MODE==0)?AD3:(MODE==1)?HID:D;
  int z=blockIdx.z;
  int Mz=(z<NE)? g_ne[z] : T;
  int m0=blockIdx.y*128;
  if(m0>=Mz) return;
  int n0=blockIdx.x*128;
  int base=(z<NE)? z*CAP : ROWS_R;

  const float* Bmat; const float* bias;
  if(MODE==0){ Bmat=(z<NE)? p.Wada_e+(size_t)z*DCND*AD3 : p.Wada_s; bias=(z<NE)? p.bada_e+z*AD3 : p.bada_s; }
  else if(MODE==1){ Bmat=(z<NE)? p.W1_e+(size_t)z*D*HID : p.W1_s; bias=(z<NE)? p.b1_e+z*HID : p.b1_s; }
  else { Bmat=(z<NE)? p.W2_e+(size_t)z*HID*D : p.W2_s; bias=(z<NE)? p.b2_e+z*D : p.b2_s; }

  int tid=threadIdx.x;
  int lr=tid>>1;            // A row within tile this thread loads
  int ak=(tid&1)*4;         // k offset of its float4
  int ar=m0+lr;

  const float* aptr;
  bool aval=true;
  if(MODE==0){
    int tok=(z<NE)? g_slot_tok[z*CAP+ar] : ar;
    aval=(tok>=0);
    aptr=p.cond+(size_t)(tok<0?0:tok)*DCND+ak;
  } else {
    const float* Abuf=(MODE==1)? g_h : g_u;
    aptr=Abuf+(size_t)(base+ar)*KD+ak;
  }
  const float* bptr=Bmat+(size_t)(tid>>5)*ND+n0+(tid&31)*4;

  __shared__ float As[8][128];
  __shared__ float Bs[8][128];

  float acc[8][8];
  #pragma unroll
  for(int i=0;i<8;i++)
    #pragma unroll
    for(int j=0;j<8;j++) acc[i][j]=0.f;

  int ty=tid>>4, tx=tid&15;

  for(int kt=0;kt<KD;kt+=8){
    float4 av = aval ? *(const float4*)aptr : make_float4(0.f,0.f,0.f,0.f);
    float4 bv = *(const float4*)bptr;
    aptr+=8;
    bptr+=(size_t)8*ND;
    As[ak+0][lr]=av.x; As[ak+1][lr]=av.y; As[ak+2][lr]=av.z; As[ak+3][lr]=av.w;
    *(float4*)&Bs[tid>>5][(tid&31)*4]=bv;
    __syncthreads();
    #pragma unroll
    for(int k=0;k<8;k++){
      float4 a0=*(float4*)&As[k][ty*8];
      float4 a1=*(float4*)&As[k][ty*8+4];
      float4 b0=*(float4*)&Bs[k][tx*8];
      float4 b1=*(float4*)&Bs[k][tx*8+4];
      float ra[8]={a0.x,a0.y,a0.z,a0.w,a1.x,a1.y,a1.z,a1.w};
      float rb[8]={b0.x,b0.y,b0.z,b0.w,b1.x,b1.y,b1.z,b1.w};
      #pragma unroll
      for(int i=0;i<8;i++)
        #pragma unroll
        for(int j=0;j<8;j++) acc[i][j]+=ra[i]*rb[j];
    }
    __syncthreads();
  }

  // -------- epilogue --------
  if(MODE==0||MODE==1){
    float* dst=(MODE==0)? g_ada : g_u;
    #pragma unroll
    for(int i=0;i<8;i++){
      int r=m0+ty*8+i;
      size_t ro=(size_t)(base+r)*ND+n0+tx*8;
      #pragma unroll
      for(int j=0;j<8;j++){
        float v=acc[i][j]+bias[n0+tx*8+j];
        if(MODE==1) v=gelu_tanh(v);
        dst[ro+j]=v;
      }
    }
  } else {
    #pragma unroll
    for(int i=0;i<8;i++){
      int r=m0+ty*8+i;
      const float* gp=&g_ada[(size_t)(base+r)*AD3+2*D+n0+tx*8];
      if(z<NE){
        int sidx=z*CAP+r;
        int tok=g_slot_tok[sidx];
        if(tok<0) continue;
        float f=g_slot_w[sidx]*p.mask[tok];
        float* mp=&g_moe[(size_t)tok*D+n0+tx*8];
        #pragma unroll
        for(int j=0;j<8;j++){
          float val=(acc[i][j]+bias[n0+tx*8+j])*gp[j]*f;
          atomicAdd(&mp[j],val);
        }
      } else {
        float f=p.mask[r];
        float* sp=&g_sy[(size_t)r*D+n0+tx*8];
        #pragma unroll
        for(int j=0;j<8;j++)
          sp[j]=(acc[i][j]+bias[n0+tx*8+j])*gp[j]*f;
      }
    }
  }
}

// ---------------- combine: out = (shared + 2*moe)/3 ----------------
__global__ void k_combine(float* __restrict__ out){
  size_t i=(size_t)blockIdx.x*blockDim.x+threadIdx.x;   // over T*D/4
  float4 s=((const float4*)g_sy)[i];
  float4 m=((const float4*)g_moe)[i];
  float4 o;
  const float inv3=1.f/3.f;
  o.x=(s.x+2.f*m.x)*inv3;
  o.y=(s.y+2.f*m.y)*inv3;
  o.z=(s.z+2.f*m.z)*inv3;
  o.w=(s.w+2.f*m.w)*inv3;
  ((float4*)out)[i]=o;
}

extern "C" void kernel_launch(void* const* d_in, const int* in_sizes, int n_in,
                              void* d_out, int out_size){
  P p;
  p.x     =(const float*)d_in[0];
  p.cond  =(const float*)d_in[1];
  p.mask  =(const float*)d_in[2];
  const float* Wg=(const float*)d_in[3];
  p.Wada_s=(const float*)d_in[4];
  p.bada_s=(const float*)d_in[5];
  p.W1_s  =(const float*)d_in[6];
  p.b1_s  =(const float*)d_in[7];
  p.W2_s  =(const float*)d_in[8];
  p.b2_s  =(const float*)d_in[9];
  p.Wada_e=(const float*)d_in[10];
  p.bada_e=(const float*)d_in[11];
  p.W1_e  =(const float*)d_in[12];
  p.b1_e  =(const float*)d_in[13];
  p.W2_e  =(const float*)d_in[14];
  p.b2_e  =(const float*)d_in[15];

  void *pslot=nullptr, *pmoe=nullptr;
  cudaGetSymbolAddress(&pslot, g_slot_tok);
  cudaGetSymbolAddress(&pmoe,  g_moe);
  cudaMemsetAsync(pslot, 0xFF, sizeof(int)*ROWS_R, 0);     // slot_tok = -1
  cudaMemsetAsync(pmoe,  0,    sizeof(float)*(size_t)T*D, 0);

  k_router <<<T/4, 128>>>(p.x, Wg);
  k_hist   <<<NCHUNK, CHUNK>>>();
  k_scan   <<<1, 32>>>();
  k_place  <<<NCHUNK, CHUNK>>>();
  k_lnstats<<<T/4, 128>>>(p.x);

  dim3 g0(AD3/128, 64, NE+1);  k_gemm<0><<<g0, 256>>>(p);
  k_mod<<<ROWS_ALL, 256>>>(p.x);
  dim3 g1(HID/128, 64, NE+1);  k_gemm<1><<<g1, 256>>>(p);
  dim3 g2(D/128,   64, NE+1);  k_gemm<2><<<g2, 256>>>(p);

  k_combine<<<(T*D/4)/256, 256>>>((float*)d_out);
}

// round 3
// speedup vs baseline: 2.2325x; 2.2325x over previous
#include <cuda_runtime.h>
#include <math.h>
#include <stdint.h>

#define T 8192
#define D 1024
#define DCND 256
#define NE 8
#define HID 4096
#define CAP 2560
#define NTOK (T*2)
#define ROWS_R (NE*CAP)
#define ROWS_ALL (ROWS_R+T)
#define AD3 3072
#define NCHUNK 64
#define CHUNK 256
#define KC 32

// ---------------- scratch (device globals; no allocations) ----------------
__device__ int   g_tope[NTOK];
__device__ float g_topw[NTOK];
__device__ int   g_hist[NCHUNK*NE];
__device__ int   g_coff[NCHUNK*NE];
__device__ int   g_tpe[NE];
__device__ int   g_starts[NE];
__device__ int   g_ne[NE];
__device__ int   g_slot_tok[ROWS_R];
__device__ float g_slot_w[ROWS_R];
__device__ float g_mu[T];
__device__ float g_rstd[T];
__device__ float g_ada[(size_t)ROWS_ALL*AD3];   // shift|scale|gate (fp32)
__device__ float g_h[(size_t)ROWS_ALL*D];       // modulated LN input (tf32-rounded)
__device__ float g_u[(size_t)ROWS_ALL*HID];     // gelu(h@W1+b1) (tf32-rounded)
__device__ float g_moe[(size_t)T*D];
__device__ float g_sy[(size_t)T*D];
// tf32-rounded copies (same [K,N] layout), experts then shared at z=NE
__device__ float g_condr[(size_t)T*DCND];
__device__ float g_wadar[(size_t)(NE+1)*DCND*AD3];
__device__ float g_w1r[(size_t)(NE+1)*D*HID];
__device__ float g_w2r[(size_t)(NE+1)*HID*D];

struct P {
  const float *x,*cond,*mask;
  const float *Wada_s,*bada_s,*W1_s,*b1_s,*W2_s,*b2_s;
  const float *Wada_e,*bada_e,*W1_e,*b1_e,*W2_e,*b2_e;
};

// ---------------- helpers ----------------
__device__ __forceinline__ float to_tf32(float x){
  float r; asm("cvt.rna.tf32.f32 %0, %1;" : "=f"(r) : "f"(x)); return r;
}
__device__ __forceinline__ uint32_t s2u(const void* p){
  uint32_t a;
  asm("{ .reg .u64 t; cvta.to.shared.u64 t, %1; cvt.u32.u64 %0, t; }" : "=r"(a) : "l"(p));
  return a;
}
__device__ __forceinline__ void cp16(uint32_t d, const void* s, uint32_t sz){
  asm volatile("cp.async.cg.shared.global [%0], [%1], 16, %2;" :: "r"(d),"l"(s),"r"(sz) : "memory");
}
__device__ __forceinline__ void mma8(float* c, const uint32_t* a, const uint32_t* b){
  asm volatile("mma.sync.aligned.m16n8k8.row.col.f32.tf32.tf32.f32 "
    "{%0,%1,%2,%3}, {%4,%5,%6,%7}, {%8,%9}, {%0,%1,%2,%3};"
    : "+f"(c[0]),"+f"(c[1]),"+f"(c[2]),"+f"(c[3])
    : "r"(a[0]),"r"(a[1]),"r"(a[2]),"r"(a[3]), "r"(b[0]),"r"(b[1]));
}

// ---------------- tf32 rounding pass ----------------
__global__ void k_round(const float* __restrict__ s, float* __restrict__ d, size_t n4){
  size_t i=(size_t)blockIdx.x*blockDim.x+threadIdx.x;
  if(i>=n4) return;
  float4 v=((const float4*)s)[i];
  v.x=to_tf32(v.x); v.y=to_tf32(v.y); v.z=to_tf32(v.z); v.w=to_tf32(v.w);
  ((float4*)d)[i]=v;
}

// ---------------- router: warp/token, top-2 of 7 ----------------
__global__ void k_router(const float* __restrict__ x, const float* __restrict__ Wg){
  int w=(blockIdx.x*blockDim.x+threadIdx.x)>>5;
  int lane=threadIdx.x&31;
  if(w>=T) return;
  const float* xr=x+(size_t)w*D;
  float a[7]={0.f,0.f,0.f,0.f,0.f,0.f,0.f};
  for(int k=lane;k<D;k+=32){
    float xv=xr[k];
    #pragma unroll
    for(int j=0;j<7;j++) a[j]+=xv*Wg[k*7+j];
  }
  #pragma unroll
  for(int j=0;j<7;j++)
    for(int o=16;o;o>>=1) a[j]+=__shfl_xor_sync(0xffffffffu,a[j],o);
  if(lane==0){
    int j0=0;
    #pragma unroll
    for(int j=1;j<7;j++) if(a[j]>a[j0]) j0=j;
    int j1=-1;
    #pragma unroll
    for(int j=0;j<7;j++){ if(j==j0) continue; if(j1<0||a[j]>a[j1]) j1=j; }
    float e1=expf(a[j1]-a[j0]);
    float inv=1.f/(1.f+e1);
    g_tope[2*w]=j0;   g_topw[2*w]=inv;
    g_tope[2*w+1]=j1; g_topw[2*w+1]=e1*inv;
  }
}

// ---------------- stable counting sort by expert ----------------
__global__ void k_hist(){
  __shared__ int cnt[NE];
  int tid=threadIdx.x;
  if(tid<NE) cnt[tid]=0;
  __syncthreads();
  atomicAdd(&cnt[g_tope[blockIdx.x*CHUNK+tid]],1);
  __syncthreads();
  if(tid<NE) g_hist[blockIdx.x*NE+tid]=cnt[tid];
}
__global__ void k_scan(){
  int tid=threadIdx.x;
  __shared__ int tpe[NE], st[NE];
  if(tid<NE){
    int s=0;
    for(int c=0;c<NCHUNK;c++) s+=g_hist[c*NE+tid];
    tpe[tid]=s; g_tpe[tid]=s; g_ne[tid]=s<CAP?s:CAP;
  }
  __syncthreads();
  if(tid==0){
    int cum=0;
    for(int e=0;e<NE;e++){ st[e]=cum; g_starts[e]=cum; cum+=tpe[e]; }
  }
  __syncthreads();
  if(tid<NE){
    int run=st[tid];
    for(int c=0;c<NCHUNK;c++){ g_coff[c*NE+tid]=run; run+=g_hist[c*NE+tid]; }
  }
}
__global__ void k_place(){
  __shared__ int se[CHUNK];
  int tid=threadIdx.x;
  int g=blockIdx.x*CHUNK+tid;
  int e=g_tope[g];
  se[tid]=e;
  __syncthreads();
  int rank=0;
  for(int j=0;j<tid;j++) rank += (se[j]==e);
  int pos=g_coff[blockIdx.x*NE+e]+rank;
  int slot=pos-g_starts[e];
  if(slot<CAP){
    g_slot_tok[e*CAP+slot]=g>>1;
    g_slot_w[e*CAP+slot]=g_topw[g];
  }
}

// ---------------- LN stats ----------------
__global__ void k_lnstats(const float* __restrict__ x){
  int w=(blockIdx.x*blockDim.x+threadIdx.x)>>5;
  int lane=threadIdx.x&31;
  if(w>=T) return;
  const float* xr=x+(size_t)w*D;
  float s=0.f,s2=0.f;
  for(int k=lane;k<D;k+=32){ float v=xr[k]; s+=v; s2+=v*v; }
  for(int o=16;o;o>>=1){
    s+=__shfl_xor_sync(0xffffffffu,s,o);
    s2+=__shfl_xor_sync(0xffffffffu,s2,o);
  }
  if(lane==0){
    float mu=s*(1.f/(float)D);
    float var=s2*(1.f/(float)D)-mu*mu;
    g_mu[w]=mu;
    g_rstd[w]=rsqrtf(var+1e-5f);
  }
}

// ---------------- modulate: h = tf32( LN(x)*(1+scale)+shift ) ----------------
__global__ void k_mod(const float* __restrict__ x){
  int r=blockIdx.x;
  int tok=(r<ROWS_R)? g_slot_tok[r] : (r-ROWS_R);
  int d4=threadIdx.x;
  float4* hp=(float4*)(g_h+(size_t)r*D);
  if(tok<0){ hp[d4]=make_float4(0.f,0.f,0.f,0.f); return; }
  const float4* xp=(const float4*)(x+(size_t)tok*D);
  float mu=g_mu[tok], rs=g_rstd[tok];
  const float* ada=g_ada+(size_t)r*AD3;
  float4 xv=xp[d4];
  float4 sh=((const float4*)ada)[d4];
  float4 sc=((const float4*)(ada+D))[d4];
  float4 h;
  h.x=to_tf32((xv.x-mu)*rs*(1.f+sc.x)+sh.x);
  h.y=to_tf32((xv.y-mu)*rs*(1.f+sc.y)+sh.y);
  h.z=to_tf32((xv.z-mu)*rs*(1.f+sc.z)+sh.z);
  h.w=to_tf32((xv.w-mu)*rs*(1.f+sc.w)+sh.w);
  hp[d4]=h;
}

__device__ __forceinline__ float gelu_tanh(float v){
  const float c=0.7978845608028654f;
  return 0.5f*v*(1.f+tanhf(c*(v+0.044715f*v*v*v)));
}

// ---------------- tf32 mma.sync GEMM, 128x128 tile, 4 warps, cp.async 2-stage ----------------
// MODE 0: ada = gather(cond_r) @ Wada_r + bada          (K=256,  N=3072)
// MODE 1: u   = tf32(gelu(g_h @ W1_r + b1))             (K=1024, N=4096)
// MODE 2: y   = g_u @ W2_r + b2 -> gate*mask*w scatter  (K=4096, N=1024)
#define APAD 36
#define BPAD 132
template<int MODE>
__global__ void __launch_bounds__(128) k_gemm_mma(P p){
  constexpr int KD=(MODE==0)?DCND:(MODE==1)?D:HID;
  constexpr int ND=(MODE==0)?AD3:(MODE==1)?HID:D;
  constexpr int NC=KD/KC;

  int z=blockIdx.z;
  int Mz=(z<NE)? g_ne[z] : T;
  int m0=blockIdx.y*128;
  if(m0>=Mz) return;
  int n0=blockIdx.x*128;
  int base=(z<NE)? z*CAP : ROWS_R;

  extern __shared__ float sm[];
  float* As=sm;                       // [2][128][APAD]
  float* Bs=sm+2*128*APAD;            // [2][KC][BPAD]
  uint32_t sa=s2u(As), sb=s2u(Bs);

  int tid=threadIdx.x, warp=tid>>5, lane=tid&31;
  int wm=warp>>1, wn=warp&1;
  int g4=lane>>2, t4=lane&3;

  const float* Wr=((MODE==0)? g_wadar : (MODE==1)? g_w1r : g_w2r)+(size_t)z*(size_t)KD*ND;
  const float* bias;
  if(MODE==0) bias=(z<NE)? p.bada_e+z*AD3 : p.bada_s;
  else if(MODE==1) bias=(z<NE)? p.b1_e+z*HID : p.b1_s;
  else bias=(z<NE)? p.b2_e+z*D : p.b2_s;

  // A loader: thread tid owns A row (m0+tid), 32 floats per chunk
  const float* pA;
  uint32_t asz=16;
  if(MODE==0){
    int tok=(z<NE)? g_slot_tok[z*CAP+m0+tid] : (m0+tid);
    if(tok<0){ tok=0; asz=0; }
    pA=g_condr+(size_t)tok*DCND;
  } else {
    const float* Ab=(MODE==1)? g_h : g_u;
    pA=Ab+(size_t)(base+m0+tid)*KD;
  }
  // B loader: thread tid: k-row tid>>2, n segment (tid&3)*32
  int kr=tid>>2, seg=tid&3;
  const float* pB=Wr+(size_t)kr*ND+n0+seg*32;

  uint32_t da0=sa+(uint32_t)(tid*APAD)*4;
  uint32_t db0=sb+(uint32_t)(kr*BPAD+seg*32)*4;

  float acc[4][8][4];
  #pragma unroll
  for(int mt=0;mt<4;mt++)
    #pragma unroll
    for(int nt=0;nt<8;nt++)
      #pragma unroll
      for(int r=0;r<4;r++) acc[mt][nt][r]=0.f;

  auto issue=[&](int c,int buf){
    uint32_t da=da0+(uint32_t)(buf*128*APAD)*4;
    const float* srcA=pA+(size_t)c*KC;
    #pragma unroll
    for(int i=0;i<8;i++) cp16(da+i*16, srcA+i*4, asz);
    uint32_t db=db0+(uint32_t)(buf*KC*BPAD)*4;
    const float* srcB=pB+(size_t)c*KC*ND;
    #pragma unroll
    for(int i=0;i<8;i++) cp16(db+i*16, srcB+i*4, 16u);
    asm volatile("cp.async.commit_group;" ::: "memory");
  };

  issue(0,0);
  for(int c=0;c<NC;c++){
    int cur=c&1;
    if(c+1<NC){
      issue(c+1,cur^1);
      asm volatile("cp.async.wait_group 1;" ::: "memory");
    } else {
      asm volatile("cp.async.wait_group 0;" ::: "memory");
    }
    __syncthreads();
    const float* Ab=As+cur*128*APAD;
    const float* Bb=Bs+cur*KC*BPAD;
    #pragma unroll
    for(int kk=0;kk<4;kk++){
      int k0=kk*8+t4;
      uint32_t af[4][4], bf[8][2];
      #pragma unroll
      for(int mt=0;mt<4;mt++){
        int rm=wm*64+mt*16+g4;
        af[mt][0]=__float_as_uint(Ab[rm*APAD+k0]);
        af[mt][1]=__float_as_uint(Ab[(rm+8)*APAD+k0]);
        af[mt][2]=__float_as_uint(Ab[rm*APAD+k0+4]);
        af[mt][3]=__float_as_uint(Ab[(rm+8)*APAD+k0+4]);
      }
      #pragma unroll
      for(int nt=0;nt<8;nt++){
        int cn=wn*64+nt*8+g4;
        bf[nt][0]=__float_as_uint(Bb[k0*BPAD+cn]);
        bf[nt][1]=__float_as_uint(Bb[(k0+4)*BPAD+cn]);
      }
      #pragma unroll
      for(int mt=0;mt<4;mt++)
        #pragma unroll
        for(int nt=0;nt<8;nt++)
          mma8(acc[mt][nt], af[mt], bf[nt]);
    }
    __syncthreads();
  }

  // ---- epilogue ----
  #pragma unroll
  for(int mt=0;mt<4;mt++){
    int r0=m0+wm*64+mt*16+g4;     // and r0+8
    #pragma unroll
    for(int half=0;half<2;half++){
      int r=r0+half*8;
      if(MODE==0||MODE==1){
        float* dst=(MODE==0)? g_ada : g_u;
        size_t ro=(size_t)(base+r)*ND;
        #pragma unroll
        for(int nt=0;nt<8;nt++){
          int col=n0+wn*64+nt*8+t4*2;
          float v0=acc[mt][nt][half*2+0]+bias[col+0];
          float v1=acc[mt][nt][half*2+1]+bias[col+1];
          if(MODE==1){ v0=to_tf32(gelu_tanh(v0)); v1=to_tf32(gelu_tanh(v1)); }
          float2 o; o.x=v0; o.y=v1;
          *(float2*)(dst+ro+col)=o;
        }
      } else {
        const float* gp=&g_ada[(size_t)(base+r)*AD3+2*D];
        if(z<NE){
          int sidx=z*CAP+r;
          int tok=g_slot_tok[sidx];
          if(tok<0) continue;
          float f=g_slot_w[sidx]*p.mask[tok];
          float* mp=&g_moe[(size_t)tok*D];
          #pragma unroll
          for(int nt=0;nt<8;nt++){
            int col=n0+wn*64+nt*8+t4*2;
            atomicAdd(&mp[col+0],(acc[mt][nt][half*2+0]+bias[col+0])*gp[col+0]*f);
            atomicAdd(&mp[col+1],(acc[mt][nt][half*2+1]+bias[col+1])*gp[col+1]*f);
          }
        } else {
          float f=p.mask[r];
          float* sp=&g_sy[(size_t)r*D];
          #pragma unroll
          for(int nt=0;nt<8;nt++){
            int col=n0+wn*64+nt*8+t4*2;
            float2 o;
            o.x=(acc[mt][nt][half*2+0]+bias[col+0])*gp[col+0]*f;
            o.y=(acc[mt][nt][half*2+1]+bias[col+1])*gp[col+1]*f;
            *(float2*)(sp+col)=o;
          }
        }
      }
    }
  }
}

// ---------------- combine: out = (shared + 2*moe)/3 ----------------
__global__ void k_combine(float* __restrict__ out){
  size_t i=(size_t)blockIdx.x*blockDim.x+threadIdx.x;
  float4 s=((const float4*)g_sy)[i];
  float4 m=((const float4*)g_moe)[i];
  float4 o;
  const float inv3=1.f/3.f;
  o.x=(s.x+2.f*m.x)*inv3;
  o.y=(s.y+2.f*m.y)*inv3;
  o.z=(s.z+2.f*m.z)*inv3;
  o.w=(s.w+2.f*m.w)*inv3;
  ((float4*)out)[i]=o;
}

extern "C" void kernel_launch(void* const* d_in, const int* in_sizes, int n_in,
                              void* d_out, int out_size){
  P p;
  p.x     =(const float*)d_in[0];
  p.cond  =(const float*)d_in[1];
  p.mask  =(const float*)d_in[2];
  const float* Wg=(const float*)d_in[3];
  p.Wada_s=(const float*)d_in[4];
  p.bada_s=(const float*)d_in[5];
  p.W1_s  =(const float*)d_in[6];
  p.b1_s  =(const float*)d_in[7];
  p.W2_s  =(const float*)d_in[8];
  p.b2_s  =(const float*)d_in[9];
  p.Wada_e=(const float*)d_in[10];
  p.bada_e=(const float*)d_in[11];
  p.W1_e  =(const float*)d_in[12];
  p.b1_e  =(const float*)d_in[13];
  p.W2_e  =(const float*)d_in[14];
  p.b2_e  =(const float*)d_in[15];

  const int SMEM_SZ=(2*128*APAD+2*KC*BPAD)*4;
  cudaFuncSetAttribute(k_gemm_mma<0>, cudaFuncAttributeMaxDynamicSharedMemorySize, SMEM_SZ);
  cudaFuncSetAttribute(k_gemm_mma<1>, cudaFuncAttributeMaxDynamicSharedMemorySize, SMEM_SZ);
  cudaFuncSetAttribute(k_gemm_mma<2>, cudaFuncAttributeMaxDynamicSharedMemorySize, SMEM_SZ);

  void *pslot=nullptr, *pmoe=nullptr;
  cudaGetSymbolAddress(&pslot, g_slot_tok);
  cudaGetSymbolAddress(&pmoe,  g_moe);
  cudaMemsetAsync(pslot, 0xFF, sizeof(int)*ROWS_R, 0);
  cudaMemsetAsync(pmoe,  0,    sizeof(float)*(size_t)T*D, 0);

  // tf32-round weights + cond into scratch copies
  void *pcr, *pwa, *pw1, *pw2;
  cudaGetSymbolAddress(&pcr, g_condr);
  cudaGetSymbolAddress(&pwa, g_wadar);
  cudaGetSymbolAddress(&pw1, g_w1r);
  cudaGetSymbolAddress(&pw2, g_w2r);
  {
    auto rnd=[&](const float* s, float* d, size_t n){
      size_t n4=n/4;
      k_round<<<(unsigned)((n4+255)/256),256>>>(s,d,n4);
    };
    rnd(p.cond,  (float*)pcr, (size_t)T*DCND);
    rnd(p.Wada_e,(float*)pwa, (size_t)NE*DCND*AD3);
    rnd(p.Wada_s,(float*)pwa+(size_t)NE*DCND*AD3, (size_t)DCND*AD3);
    rnd(p.W1_e,  (float*)pw1, (size_t)NE*D*HID);
    rnd(p.W1_s,  (float*)pw1+(size_t)NE*D*HID, (size_t)D*HID);
    rnd(p.W2_e,  (float*)pw2, (size_t)NE*HID*D);
    rnd(p.W2_s,  (float*)pw2+(size_t)NE*HID*D, (size_t)HID*D);
  }

  k_router <<<T/4, 128>>>(p.x, Wg);
  k_hist   <<<NCHUNK, CHUNK>>>();
  k_scan   <<<1, 32>>>();
  k_place  <<<NCHUNK, CHUNK>>>();
  k_lnstats<<<T/4, 128>>>(p.x);

  dim3 g0(AD3/128, 64, NE+1);  k_gemm_mma<0><<<g0, 128, SMEM_SZ>>>(p);
  k_mod<<<ROWS_ALL, 256>>>(p.x);
  dim3 g1(HID/128, 64, NE+1);  k_gemm_mma<1><<<g1, 128, SMEM_SZ>>>(p);
  dim3 g2(D/128,   64, NE+1);  k_gemm_mma<2><<<g2, 128, SMEM_SZ>>>(p);

  k_combine<<<(T*D/4)/256, 256>>>((float*)d_out);
}

// round 4
// speedup vs baseline: 2.3119x; 1.0356x over previous
#include <cuda_runtime.h>
#include <math.h>
#include <stdint.h>

#define T 8192
#define D 1024
#define DCND 256
#define NE 8
#define HID 4096
#define CAP 2560
#define NTOK (T*2)
#define ROWS_R (NE*CAP)
#define ROWS_ALL (ROWS_R+T)
#define AD3 3072
#define NCHUNK 64
#define CHUNK 256
#define KC 32
#define PADR 36               // floats per smem row (32 + 4 pad) = 144B

// ---------------- scratch (device globals; no allocations) ----------------
__device__ int   g_tope[NTOK];
__device__ float g_topw[NTOK];
__device__ int   g_hist[NCHUNK*NE];
__device__ int   g_coff[NCHUNK*NE];
__device__ int   g_tpe[NE];
__device__ int   g_starts[NE];
__device__ int   g_ne[NE];
__device__ int   g_slot_tok[ROWS_R];
__device__ float g_slot_w[ROWS_R];
__device__ float g_mu[T];
__device__ float g_rstd[T];
__device__ float g_ada[(size_t)ROWS_ALL*AD3];   // shift|scale|gate (fp32)
__device__ float g_h[(size_t)ROWS_ALL*D];       // modulated LN input (tf32-rounded)
__device__ float g_u[(size_t)ROWS_ALL*HID];     // gelu(h@W1+b1) (tf32-rounded)
__device__ float g_moe[(size_t)T*D];
__device__ float g_sy[(size_t)T*D];
__device__ float g_condr[(size_t)T*DCND];       // tf32-rounded cond
// transposed [z][N][K], tf32-rounded weights
__device__ float g_wadat[(size_t)(NE+1)*AD3*DCND];
__device__ float g_w1t[(size_t)(NE+1)*HID*D];
__device__ float g_w2t[(size_t)(NE+1)*D*HID];

struct P {
  const float *x,*cond,*mask;
  const float *Wada_s,*bada_s,*W1_s,*b1_s,*W2_s,*b2_s;
  const float *Wada_e,*bada_e,*W1_e,*b1_e,*W2_e,*b2_e;
};

// ---------------- helpers ----------------
__device__ __forceinline__ float to_tf32(float x){
  float r; asm("cvt.rna.tf32.f32 %0, %1;" : "=f"(r) : "f"(x)); return r;
}
__device__ __forceinline__ uint32_t s2u(const void* p){
  uint32_t a;
  asm("{ .reg .u64 t; cvta.to.shared.u64 t, %1; cvt.u32.u64 %0, t; }" : "=r"(a) : "l"(p));
  return a;
}
__device__ __forceinline__ void cp16(uint32_t d, const void* s, uint32_t sz){
  asm volatile("cp.async.cg.shared.global [%0], [%1], 16, %2;" :: "r"(d),"l"(s),"r"(sz) : "memory");
}
__device__ __forceinline__ void mma8(float* c, const uint32_t* a, const uint32_t* b){
  asm volatile("mma.sync.aligned.m16n8k8.row.col.f32.tf32.tf32.f32 "
    "{%0,%1,%2,%3}, {%4,%5,%6,%7}, {%8,%9}, {%0,%1,%2,%3};"
    : "+f"(c[0]),"+f"(c[1]),"+f"(c[2]),"+f"(c[3])
    : "r"(a[0]),"r"(a[1]),"r"(a[2]),"r"(a[3]), "r"(b[0]),"r"(b[1]));
}
__device__ __forceinline__ void ldsm4(uint32_t* r, uint32_t a){
  asm volatile("ldmatrix.sync.aligned.m8n8.x4.shared.b16 {%0,%1,%2,%3}, [%4];"
    : "=r"(r[0]),"=r"(r[1]),"=r"(r[2]),"=r"(r[3]) : "r"(a));
}

// ---------------- tf32 rounding pass (cond only) ----------------
__global__ void k_round(const float* __restrict__ s, float* __restrict__ d, size_t n4){
  size_t i=(size_t)blockIdx.x*blockDim.x+threadIdx.x;
  if(i>=n4) return;
  float4 v=((const float4*)s)[i];
  v.x=to_tf32(v.x); v.y=to_tf32(v.y); v.z=to_tf32(v.z); v.w=to_tf32(v.w);
  ((float4*)d)[i]=v;
}

// ---------------- weight transpose [K,N]->[N,K] + tf32 round ----------------
template<int MODE>
__global__ void k_wt(P p){
  constexpr int KD=(MODE==0)?DCND:(MODE==1)?D:HID;
  constexpr int ND=(MODE==0)?AD3:(MODE==1)?HID:D;
  int z=blockIdx.z;
  const float* W;
  if(MODE==0) W=(z<NE)? p.Wada_e+(size_t)z*KD*ND : p.Wada_s;
  else if(MODE==1) W=(z<NE)? p.W1_e+(size_t)z*KD*ND : p.W1_s;
  else W=(z<NE)? p.W2_e+(size_t)z*KD*ND : p.W2_s;
  float* Wt=((MODE==0)? g_wadat : (MODE==1)? g_w1t : g_w2t)+(size_t)z*KD*ND;
  __shared__ float t[32][33];
  int n0=blockIdx.x*32, k0=blockIdx.y*32;
  int tx=threadIdx.x, ty=threadIdx.y;
  #pragma unroll
  for(int i=0;i<32;i+=8)
    t[ty+i][tx]=W[(size_t)(k0+ty+i)*ND+n0+tx];
  __syncthreads();
  #pragma unroll
  for(int i=0;i<32;i+=8)
    Wt[(size_t)(n0+ty+i)*KD+k0+tx]=to_tf32(t[tx][ty+i]);
}

// ---------------- router: warp/token, top-2 of 7 ----------------
__global__ void k_router(const float* __restrict__ x, const float* __restrict__ Wg){
  int w=(blockIdx.x*blockDim.x+threadIdx.x)>>5;
  int lane=threadIdx.x&31;
  if(w>=T) return;
  const float* xr=x+(size_t)w*D;
  float a[7]={0.f,0.f,0.f,0.f,0.f,0.f,0.f};
  for(int k=lane;k<D;k+=32){
    float xv=xr[k];
    #pragma unroll
    for(int j=0;j<7;j++) a[j]+=xv*Wg[k*7+j];
  }
  #pragma unroll
  for(int j=0;j<7;j++)
    for(int o=16;o;o>>=1) a[j]+=__shfl_xor_sync(0xffffffffu,a[j],o);
  if(lane==0){
    int j0=0;
    #pragma unroll
    for(int j=1;j<7;j++) if(a[j]>a[j0]) j0=j;
    int j1=-1;
    #pragma unroll
    for(int j=0;j<7;j++){ if(j==j0) continue; if(j1<0||a[j]>a[j1]) j1=j; }
    float e1=expf(a[j1]-a[j0]);
    float inv=1.f/(1.f+e1);
    g_tope[2*w]=j0;   g_topw[2*w]=inv;
    g_tope[2*w+1]=j1; g_topw[2*w+1]=e1*inv;
  }
}

// ---------------- stable counting sort by expert ----------------
__global__ void k_hist(){
  __shared__ int cnt[NE];
  int tid=threadIdx.x;
  if(tid<NE) cnt[tid]=0;
  __syncthreads();
  atomicAdd(&cnt[g_tope[blockIdx.x*CHUNK+tid]],1);
  __syncthreads();
  if(tid<NE) g_hist[blockIdx.x*NE+tid]=cnt[tid];
}
__global__ void k_scan(){
  int tid=threadIdx.x;
  __shared__ int tpe[NE], st[NE];
  if(tid<NE){
    int s=0;
    for(int c=0;c<NCHUNK;c++) s+=g_hist[c*NE+tid];
    tpe[tid]=s; g_tpe[tid]=s; g_ne[tid]=s<CAP?s:CAP;
  }
  __syncthreads();
  if(tid==0){
    int cum=0;
    for(int e=0;e<NE;e++){ st[e]=cum; g_starts[e]=cum; cum+=tpe[e]; }
  }
  __syncthreads();
  if(tid<NE){
    int run=st[tid];
    for(int c=0;c<NCHUNK;c++){ g_coff[c*NE+tid]=run; run+=g_hist[c*NE+tid]; }
  }
}
__global__ void k_place(){
  __shared__ int se[CHUNK];
  int tid=threadIdx.x;
  int g=blockIdx.x*CHUNK+tid;
  int e=g_tope[g];
  se[tid]=e;
  __syncthreads();
  int rank=0;
  for(int j=0;j<tid;j++) rank += (se[j]==e);
  int pos=g_coff[blockIdx.x*NE+e]+rank;
  int slot=pos-g_starts[e];
  if(slot<CAP){
    g_slot_tok[e*CAP+slot]=g>>1;
    g_slot_w[e*CAP+slot]=g_topw[g];
  }
}

// ---------------- LN stats ----------------
__global__ void k_lnstats(const float* __restrict__ x){
  int w=(blockIdx.x*blockDim.x+threadIdx.x)>>5;
  int lane=threadIdx.x&31;
  if(w>=T) return;
  const float* xr=x+(size_t)w*D;
  float s=0.f,s2=0.f;
  for(int k=lane;k<D;k+=32){ float v=xr[k]; s+=v; s2+=v*v; }
  for(int o=16;o;o>>=1){
    s+=__shfl_xor_sync(0xffffffffu,s,o);
    s2+=__shfl_xor_sync(0xffffffffu,s2,o);
  }
  if(lane==0){
    float mu=s*(1.f/(float)D);
    float var=s2*(1.f/(float)D)-mu*mu;
    g_mu[w]=mu;
    g_rstd[w]=rsqrtf(var+1e-5f);
  }
}

// ---------------- modulate: h = tf32( LN(x)*(1+scale)+shift ) ----------------
__global__ void k_mod(const float* __restrict__ x){
  int r=blockIdx.x;
  int tok=(r<ROWS_R)? g_slot_tok[r] : (r-ROWS_R);
  int d4=threadIdx.x;
  float4* hp=(float4*)(g_h+(size_t)r*D);
  if(tok<0){ hp[d4]=make_float4(0.f,0.f,0.f,0.f); return; }
  const float4* xp=(const float4*)(x+(size_t)tok*D);
  float mu=g_mu[tok], rs=g_rstd[tok];
  const float* ada=g_ada+(size_t)r*AD3;
  float4 xv=xp[d4];
  float4 sh=((const float4*)ada)[d4];
  float4 sc=((const float4*)(ada+D))[d4];
  float4 h;
  h.x=to_tf32((xv.x-mu)*rs*(1.f+sc.x)+sh.x);
  h.y=to_tf32((xv.y-mu)*rs*(1.f+sc.y)+sh.y);
  h.z=to_tf32((xv.z-mu)*rs*(1.f+sc.z)+sh.z);
  h.w=to_tf32((xv.w-mu)*rs*(1.f+sc.w)+sh.w);
  hp[d4]=h;
}

__device__ __forceinline__ float gelu_tanh(float v){
  const float c=0.7978845608028654f;
  return 0.5f*v*(1.f+tanhf(c*(v+0.044715f*v*v*v)));
}

// ---------------- tf32 mma.sync GEMM, 128x128 tile, ldmatrix fragments ----------------
// A smem [2][128][PADR] rows=M, B smem [2][128][PADR] rows=N (weights pre-transposed [N][K])
// MODE 0: ada = gather(cond_r) @ Wada + bada            (K=256,  N=3072)
// MODE 1: u   = tf32(gelu(g_h @ W1 + b1))               (K=1024, N=4096)
// MODE 2: y   = g_u @ W2 + b2 -> gate*mask*w scatter    (K=4096, N=1024)
template<int MODE>
__global__ void __launch_bounds__(128,2) k_gemm_mma(P p){
  constexpr int KD=(MODE==0)?DCND:(MODE==1)?D:HID;
  constexpr int ND=(MODE==0)?AD3:(MODE==1)?HID:D;
  constexpr int NC=KD/KC;
  constexpr uint32_t BUF=128*PADR*4;    // 18432 B per stage per operand

  int z=blockIdx.z;
  int Mz=(z<NE)? g_ne[z] : T;
  int m0=blockIdx.y*128;
  if(m0>=Mz) return;
  int n0=blockIdx.x*128;
  int base=(z<NE)? z*CAP : ROWS_R;

  extern __shared__ float sm[];
  uint32_t sa=s2u(sm);
  uint32_t sb=sa+2*BUF;

  int tid=threadIdx.x, warp=tid>>5, lane=tid&31;
  int wm=warp>>1, wn=warp&1;
  int g4=lane>>2, t4=lane&3;
  int tsel=lane>>3, tr=lane&7;

  const float* Wt=((MODE==0)? g_wadat : (MODE==1)? g_w1t : g_w2t)+(size_t)z*(size_t)KD*ND;
  const float* bias;
  if(MODE==0) bias=(z<NE)? p.bada_e+z*AD3 : p.bada_s;
  else if(MODE==1) bias=(z<NE)? p.b1_e+z*HID : p.b1_s;
  else bias=(z<NE)? p.b2_e+z*D : p.b2_s;

  // A loader: thread tid owns A row (m0+tid)
  const float* pA;
  uint32_t asz=16;
  if(MODE==0){
    int tok=(z<NE)? g_slot_tok[z*CAP+m0+tid] : (m0+tid);
    if(tok<0){ tok=0; asz=0; }
    pA=g_condr+(size_t)tok*DCND;
  } else {
    const float* Ab=(MODE==1)? g_h : g_u;
    pA=Ab+(size_t)(base+m0+tid)*KD;
  }
  // B loader: thread tid owns N row (n0+tid) of [N][K] weights
  const float* pB=Wt+(size_t)(n0+tid)*KD;

  uint32_t da0=sa+(uint32_t)tid*PADR*4;
  uint32_t db0=sb+(uint32_t)tid*PADR*4;

  // ldmatrix lane base addresses (within buffer 0)
  uint32_t abase=sa+(uint32_t)(((wm*64+(tsel&1)*8+tr)*PADR+(tsel>>1)*4)*4);
  uint32_t bbase=sb+(uint32_t)(((wn*64+(tsel>>1)*8+tr)*PADR+(tsel&1)*4)*4);

  float acc[4][8][4];
  #pragma unroll
  for(int mt=0;mt<4;mt++)
    #pragma unroll
    for(int nt=0;nt<8;nt++)
      #pragma unroll
      for(int r=0;r<4;r++) acc[mt][nt][r]=0.f;

  auto issue=[&](int c,int buf){
    uint32_t da=da0+buf*BUF;
    const float* srcA=pA+(size_t)c*KC;
    #pragma unroll
    for(int i=0;i<8;i++) cp16(da+i*16, srcA+i*4, asz);
    uint32_t db=db0+buf*BUF;
    const float* srcB=pB+(size_t)c*KC;
    #pragma unroll
    for(int i=0;i<8;i++) cp16(db+i*16, srcB+i*4, 16u);
    asm volatile("cp.async.commit_group;" ::: "memory");
  };

  issue(0,0);
  for(int c=0;c<NC;c++){
    int cur=c&1;
    if(c+1<NC){
      issue(c+1,cur^1);
      asm volatile("cp.async.wait_group 1;" ::: "memory");
    } else {
      asm volatile("cp.async.wait_group 0;" ::: "memory");
    }
    __syncthreads();
    uint32_t ao=abase+cur*BUF;
    uint32_t bo=bbase+cur*BUF;
    #pragma unroll
    for(int kk=0;kk<4;kk++){
      uint32_t af[4][4], bf[4][4];
      #pragma unroll
      for(int mt=0;mt<4;mt++) ldsm4(af[mt], ao+(uint32_t)((mt*16*PADR+kk*8)*4));
      #pragma unroll
      for(int np=0;np<4;np++) ldsm4(bf[np], bo+(uint32_t)((np*16*PADR+kk*8)*4));
      #pragma unroll
      for(int mt=0;mt<4;mt++)
        #pragma unroll
        for(int np=0;np<4;np++){
          mma8(acc[mt][2*np+0], af[mt], &bf[np][0]);
          mma8(acc[mt][2*np+1], af[mt], &bf[np][2]);
        }
    }
    __syncthreads();
  }

  // ---- epilogue ----
  #pragma unroll
  for(int mt=0;mt<4;mt++){
    int r0=m0+wm*64+mt*16+g4;
    #pragma unroll
    for(int half=0;half<2;half++){
      int r=r0+half*8;
      if(MODE==0||MODE==1){
        float* dst=(MODE==0)? g_ada : g_u;
        size_t ro=(size_t)(base+r)*ND;
        #pragma unroll
        for(int nt=0;nt<8;nt++){
          int col=n0+wn*64+nt*8+t4*2;
          float v0=acc[mt][nt][half*2+0]+bias[col+0];
          float v1=acc[mt][nt][half*2+1]+bias[col+1];
          if(MODE==1){ v0=to_tf32(gelu_tanh(v0)); v1=to_tf32(gelu_tanh(v1)); }
          float2 o; o.x=v0; o.y=v1;
          *(float2*)(dst+ro+col)=o;
        }
      } else {
        const float* gp=&g_ada[(size_t)(base+r)*AD3+2*D];
        if(z<NE){
          int sidx=z*CAP+r;
          int tok=g_slot_tok[sidx];
          if(tok<0) continue;
          float f=g_slot_w[sidx]*p.mask[tok];
          float* mp=&g_moe[(size_t)tok*D];
          #pragma unroll
          for(int nt=0;nt<8;nt++){
            int col=n0+wn*64+nt*8+t4*2;
            atomicAdd(&mp[col+0],(acc[mt][nt][half*2+0]+bias[col+0])*gp[col+0]*f);
            atomicAdd(&mp[col+1],(acc[mt][nt][half*2+1]+bias[col+1])*gp[col+1]*f);
          }
        } else {
          float f=p.mask[r];
          float* sp=&g_sy[(size_t)r*D];
          #pragma unroll
          for(int nt=0;nt<8;nt++){
            int col=n0+wn*64+nt*8+t4*2;
            float2 o;
            o.x=(acc[mt][nt][half*2+0]+bias[col+0])*gp[col+0]*f;
            o.y=(acc[mt][nt][half*2+1]+bias[col+1])*gp[col+1]*f;
            *(float2*)(sp+col)=o;
          }
        }
      }
    }
  }
}

// ---------------- combine: out = (shared + 2*moe)/3 ----------------
__global__ void k_combine(float* __restrict__ out){
  size_t i=(size_t)blockIdx.x*blockDim.x+threadIdx.x;
  float4 s=((const float4*)g_sy)[i];
  float4 m=((const float4*)g_moe)[i];
  float4 o;
  const float inv3=1.f/3.f;
  o.x=(s.x+2.f*m.x)*inv3;
  o.y=(s.y+2.f*m.y)*inv3;
  o.z=(s.z+2.f*m.z)*inv3;
  o.w=(s.w+2.f*m.w)*inv3;
  ((float4*)out)[i]=o;
}

extern "C" void kernel_launch(void* const* d_in, const int* in_sizes, int n_in,
                              void* d_out, int out_size){
  P p;
  p.x     =(const float*)d_in[0];
  p.cond  =(const float*)d_in[1];
  p.mask  =(const float*)d_in[2];
  const float* Wg=(const float*)d_in[3];
  p.Wada_s=(const float*)d_in[4];
  p.bada_s=(const float*)d_in[5];
  p.W1_s  =(const float*)d_in[6];
  p.b1_s  =(const float*)d_in[7];
  p.W2_s  =(const float*)d_in[8];
  p.b2_s  =(const float*)d_in[9];
  p.Wada_e=(const float*)d_in[10];
  p.bada_e=(const float*)d_in[11];
  p.W1_e  =(const float*)d_in[12];
  p.b1_e  =(const float*)d_in[13];
  p.W2_e  =(const float*)d_in[14];
  p.b2_e  =(const float*)d_in[15];

  const int SMEM_SZ=4*128*PADR*4;   // 73728 B
  cudaFuncSetAttribute(k_gemm_mma<0>, cudaFuncAttributeMaxDynamicSharedMemorySize, SMEM_SZ);
  cudaFuncSetAttribute(k_gemm_mma<1>, cudaFuncAttributeMaxDynamicSharedMemorySize, SMEM_SZ);
  cudaFuncSetAttribute(k_gemm_mma<2>, cudaFuncAttributeMaxDynamicSharedMemorySize, SMEM_SZ);

  void *pslot=nullptr, *pmoe=nullptr, *pcr=nullptr;
  cudaGetSymbolAddress(&pslot, g_slot_tok);
  cudaGetSymbolAddress(&pmoe,  g_moe);
  cudaGetSymbolAddress(&pcr,   g_condr);
  cudaMemsetAsync(pslot, 0xFF, sizeof(int)*ROWS_R, 0);
  cudaMemsetAsync(pmoe,  0,    sizeof(float)*(size_t)T*D, 0);

  // tf32-round cond; transpose+round all weights to [N][K]
  {
    size_t n4=(size_t)T*DCND/4;
    k_round<<<(unsigned)((n4+255)/256),256>>>(p.cond,(float*)pcr,n4);
    dim3 b(32,8);
    dim3 ga(AD3/32, DCND/32, NE+1); k_wt<0><<<ga,b>>>(p);
    dim3 g1(HID/32, D/32,   NE+1);  k_wt<1><<<g1,b>>>(p);
    dim3 g2(D/32,   HID/32, NE+1);  k_wt<2><<<g2,b>>>(p);
  }

  k_router <<<T/4, 128>>>(p.x, Wg);
  k_hist   <<<NCHUNK, CHUNK>>>();
  k_scan   <<<1, 32>>>();
  k_place  <<<NCHUNK, CHUNK>>>();
  k_lnstats<<<T/4, 128>>>(p.x);

  dim3 g0(AD3/128, 64, NE+1);  k_gemm_mma<0><<<g0, 128, SMEM_SZ>>>(p);
  k_mod<<<ROWS_ALL, 256>>>(p.x);
  dim3 g1(HID/128, 64, NE+1);  k_gemm_mma<1><<<g1, 128, SMEM_SZ>>>(p);
  dim3 g2(D/128,   64, NE+1);  k_gemm_mma<2><<<g2, 128, SMEM_SZ>>>(p);

  k_combine<<<(T*D/4)/256, 256>>>((float*)d_out);
}

// round 5
// speedup vs baseline: 4.1305x; 1.7866x over previous
#include <cuda_runtime.h>
#include <cuda_fp16.h>
#include <math.h>
#include <stdint.h>

#define T 8192
#define D 1024
#define DCND 256
#define NE 8
#define HID 4096
#define CAP 2560
#define NTOK (T*2)
#define ROWS_R (NE*CAP)
#define ROWS_ALL (ROWS_R+T)
#define AD3 3072
#define NCHUNK 64
#define CHUNK 256
#define KC 64                 // K elements (halves) per chunk = 128B/row
#define PADH 72               // halves per smem row (64 + 8 pad) = 144B

// ---------------- scratch (device globals; no allocations) ----------------
__device__ int   g_tope[NTOK];
__device__ float g_topw[NTOK];
__device__ int   g_hist[NCHUNK*NE];
__device__ int   g_coff[NCHUNK*NE];
__device__ int   g_tpe[NE];
__device__ int   g_starts[NE];
__device__ int   g_ne[NE];
__device__ int   g_slot_tok[ROWS_R];
__device__ float g_slot_w[ROWS_R];
__device__ float g_mu[T];
__device__ float g_rstd[T];
__device__ float g_ada[(size_t)ROWS_ALL*AD3];    // shift|scale|gate (fp32)
__device__ __half g_h[(size_t)ROWS_ALL*D];       // modulated LN input (fp16)
__device__ __half g_u[(size_t)ROWS_ALL*HID];     // gelu(h@W1+b1) (fp16)
__device__ float g_moe[(size_t)T*D];
__device__ float g_sy[(size_t)T*D];
__device__ __half g_condh[(size_t)T*DCND];       // fp16 cond
// transposed [z][N][K] fp16 weights
__device__ __half g_wadat[(size_t)(NE+1)*AD3*DCND];
__device__ __half g_w1t[(size_t)(NE+1)*HID*D];
__device__ __half g_w2t[(size_t)(NE+1)*D*HID];

struct P {
  const float *x,*cond,*mask;
  const float *Wada_s,*bada_s,*W1_s,*b1_s,*W2_s,*b2_s;
  const float *Wada_e,*bada_e,*W1_e,*b1_e,*W2_e,*b2_e;
};

// ---------------- helpers ----------------
__device__ __forceinline__ uint32_t s2u(const void* p){
  uint32_t a;
  asm("{ .reg .u64 t; cvta.to.shared.u64 t, %1; cvt.u32.u64 %0, t; }" : "=r"(a) : "l"(p));
  return a;
}
__device__ __forceinline__ void cp16(uint32_t d, const void* s, uint32_t sz){
  asm volatile("cp.async.cg.shared.global [%0], [%1], 16, %2;" :: "r"(d),"l"(s),"r"(sz) : "memory");
}
__device__ __forceinline__ void mma16(float* c, const uint32_t* a, const uint32_t* b){
  asm volatile("mma.sync.aligned.m16n8k16.row.col.f32.f16.f16.f32 "
    "{%0,%1,%2,%3}, {%4,%5,%6,%7}, {%8,%9}, {%0,%1,%2,%3};"
    : "+f"(c[0]),"+f"(c[1]),"+f"(c[2]),"+f"(c[3])
    : "r"(a[0]),"r"(a[1]),"r"(a[2]),"r"(a[3]), "r"(b[0]),"r"(b[1]));
}
__device__ __forceinline__ void ldsm4(uint32_t* r, uint32_t a){
  asm volatile("ldmatrix.sync.aligned.m8n8.x4.shared.b16 {%0,%1,%2,%3}, [%4];"
    : "=r"(r[0]),"=r"(r[1]),"=r"(r[2]),"=r"(r[3]) : "r"(a));
}

// ---------------- f32 -> f16 copy (cond) ----------------
__global__ void k_tohalf(const float* __restrict__ s, __half* __restrict__ d, size_t n4){
  size_t i=(size_t)blockIdx.x*blockDim.x+threadIdx.x;
  if(i>=n4) return;
  float4 v=((const float4*)s)[i];
  __half2 lo=__floats2half2_rn(v.x,v.y);
  __half2 hi=__floats2half2_rn(v.z,v.w);
  uint2 o; o.x=*(uint32_t*)&lo; o.y=*(uint32_t*)&hi;
  ((uint2*)d)[i]=o;
}

// ---------------- weight transpose [K,N]->[N,K] fp16 ----------------
template<int MODE>
__global__ void k_wt(P p){
  constexpr int KD=(MODE==0)?DCND:(MODE==1)?D:HID;
  constexpr int ND=(MODE==0)?AD3:(MODE==1)?HID:D;
  int z=blockIdx.z;
  const float* W;
  if(MODE==0) W=(z<NE)? p.Wada_e+(size_t)z*KD*ND : p.Wada_s;
  else if(MODE==1) W=(z<NE)? p.W1_e+(size_t)z*KD*ND : p.W1_s;
  else W=(z<NE)? p.W2_e+(size_t)z*KD*ND : p.W2_s;
  __half* Wt=((MODE==0)? g_wadat : (MODE==1)? g_w1t : g_w2t)+(size_t)z*KD*ND;
  __shared__ float t[32][33];
  int n0=blockIdx.x*32, k0=blockIdx.y*32;
  int tx=threadIdx.x, ty=threadIdx.y;
  #pragma unroll
  for(int i=0;i<32;i+=8)
    t[ty+i][tx]=W[(size_t)(k0+ty+i)*ND+n0+tx];
  __syncthreads();
  #pragma unroll
  for(int i=0;i<32;i+=8)
    Wt[(size_t)(n0+ty+i)*KD+k0+tx]=__float2half_rn(t[tx][ty+i]);
}

// ---------------- router: warp/token, top-2 of 7 ----------------
__global__ void k_router(const float* __restrict__ x, const float* __restrict__ Wg){
  int w=(blockIdx.x*blockDim.x+threadIdx.x)>>5;
  int lane=threadIdx.x&31;
  if(w>=T) return;
  const float* xr=x+(size_t)w*D;
  float a[7]={0.f,0.f,0.f,0.f,0.f,0.f,0.f};
  for(int k=lane;k<D;k+=32){
    float xv=xr[k];
    #pragma unroll
    for(int j=0;j<7;j++) a[j]+=xv*Wg[k*7+j];
  }
  #pragma unroll
  for(int j=0;j<7;j++)
    for(int o=16;o;o>>=1) a[j]+=__shfl_xor_sync(0xffffffffu,a[j],o);
  if(lane==0){
    int j0=0;
    #pragma unroll
    for(int j=1;j<7;j++) if(a[j]>a[j0]) j0=j;
    int j1=-1;
    #pragma unroll
    for(int j=0;j<7;j++){ if(j==j0) continue; if(j1<0||a[j]>a[j1]) j1=j; }
    float e1=expf(a[j1]-a[j0]);
    float inv=1.f/(1.f+e1);
    g_tope[2*w]=j0;   g_topw[2*w]=inv;
    g_tope[2*w+1]=j1; g_topw[2*w+1]=e1*inv;
  }
}

// ---------------- stable counting sort by expert ----------------
__global__ void k_hist(){
  __shared__ int cnt[NE];
  int tid=threadIdx.x;
  if(tid<NE) cnt[tid]=0;
  __syncthreads();
  atomicAdd(&cnt[g_tope[blockIdx.x*CHUNK+tid]],1);
  __syncthreads();
  if(tid<NE) g_hist[blockIdx.x*NE+tid]=cnt[tid];
}
__global__ void k_scan(){
  int tid=threadIdx.x;
  __shared__ int tpe[NE], st[NE];
  if(tid<NE){
    int s=0;
    for(int c=0;c<NCHUNK;c++) s+=g_hist[c*NE+tid];
    tpe[tid]=s; g_tpe[tid]=s; g_ne[tid]=s<CAP?s:CAP;
  }
  __syncthreads();
  if(tid==0){
    int cum=0;
    for(int e=0;e<NE;e++){ st[e]=cum; g_starts[e]=cum; cum+=tpe[e]; }
  }
  __syncthreads();
  if(tid<NE){
    int run=st[tid];
    for(int c=0;c<NCHUNK;c++){ g_coff[c*NE+tid]=run; run+=g_hist[c*NE+tid]; }
  }
}
__global__ void k_place(){
  __shared__ int se[CHUNK];
  int tid=threadIdx.x;
  int g=blockIdx.x*CHUNK+tid;
  int e=g_tope[g];
  se[tid]=e;
  __syncthreads();
  int rank=0;
  for(int j=0;j<tid;j++) rank += (se[j]==e);
  int pos=g_coff[blockIdx.x*NE+e]+rank;
  int slot=pos-g_starts[e];
  if(slot<CAP){
    g_slot_tok[e*CAP+slot]=g>>1;
    g_slot_w[e*CAP+slot]=g_topw[g];
  }
}

// ---------------- LN stats ----------------
__global__ void k_lnstats(const float* __restrict__ x){
  int w=(blockIdx.x*blockDim.x+threadIdx.x)>>5;
  int lane=threadIdx.x&31;
  if(w>=T) return;
  const float* xr=x+(size_t)w*D;
  float s=0.f,s2=0.f;
  for(int k=lane;k<D;k+=32){ float v=xr[k]; s+=v; s2+=v*v; }
  for(int o=16;o;o>>=1){
    s+=__shfl_xor_sync(0xffffffffu,s,o);
    s2+=__shfl_xor_sync(0xffffffffu,s2,o);
  }
  if(lane==0){
    float mu=s*(1.f/(float)D);
    float var=s2*(1.f/(float)D)-mu*mu;
    g_mu[w]=mu;
    g_rstd[w]=rsqrtf(var+1e-5f);
  }
}

// ---------------- modulate: h = f16( LN(x)*(1+scale)+shift ) ----------------
__global__ void k_mod(const float* __restrict__ x){
  int r=blockIdx.x;
  int tok=(r<ROWS_R)? g_slot_tok[r] : (r-ROWS_R);
  int d4=threadIdx.x;
  uint2* hp=(uint2*)(g_h+(size_t)r*D);
  if(tok<0){ uint2 zz; zz.x=0u; zz.y=0u; hp[d4]=zz; return; }
  const float4* xp=(const float4*)(x+(size_t)tok*D);
  float mu=g_mu[tok], rs=g_rstd[tok];
  const float* ada=g_ada+(size_t)r*AD3;
  float4 xv=xp[d4];
  float4 sh=((const float4*)ada)[d4];
  float4 sc=((const float4*)(ada+D))[d4];
  float h0=(xv.x-mu)*rs*(1.f+sc.x)+sh.x;
  float h1=(xv.y-mu)*rs*(1.f+sc.y)+sh.y;
  float h2=(xv.z-mu)*rs*(1.f+sc.z)+sh.z;
  float h3=(xv.w-mu)*rs*(1.f+sc.w)+sh.w;
  __half2 lo=__floats2half2_rn(h0,h1);
  __half2 hi=__floats2half2_rn(h2,h3);
  uint2 o; o.x=*(uint32_t*)&lo; o.y=*(uint32_t*)&hi;
  hp[d4]=o;
}

__device__ __forceinline__ float gelu_tanh(float v){
  const float c=0.7978845608028654f;
  return 0.5f*v*(1.f+tanhf(c*(v+0.044715f*v*v*v)));
}

// ---------------- fp16 mma.sync GEMM, 128x128 tile, ldmatrix fragments ----------------
// A smem [2][128][PADH] rows=M, B smem [2][128][PADH] rows=N (weights [N][K] fp16)
// MODE 0: ada = gather(condh) @ Wada + bada             (K=256,  N=3072)
// MODE 1: u   = f16(gelu(g_h @ W1 + b1))                (K=1024, N=4096)
// MODE 2: y   = g_u @ W2 + b2 -> gate*mask*w scatter    (K=4096, N=1024)
template<int MODE>
__global__ void __launch_bounds__(128,2) k_gemm_mma(P p){
  constexpr int KD=(MODE==0)?DCND:(MODE==1)?D:HID;
  constexpr int ND=(MODE==0)?AD3:(MODE==1)?HID:D;
  constexpr int NC=KD/KC;
  constexpr uint32_t BUF=128*PADH*2;    // 18432 B per stage per operand

  int z=blockIdx.z;
  int Mz=(z<NE)? g_ne[z] : T;
  int m0=blockIdx.y*128;
  if(m0>=Mz) return;
  int n0=blockIdx.x*128;
  int base=(z<NE)? z*CAP : ROWS_R;

  extern __shared__ __half smh[];
  uint32_t sa=s2u(smh);
  uint32_t sb=sa+2*BUF;

  int tid=threadIdx.x, warp=tid>>5, lane=tid&31;
  int wm=warp>>1, wn=warp&1;
  int g4=lane>>2, t4=lane&3;
  int tsel=lane>>3, tr=lane&7;

  const __half* Wt=((MODE==0)? g_wadat : (MODE==1)? g_w1t : g_w2t)+(size_t)z*(size_t)KD*ND;
  const float* bias;
  if(MODE==0) bias=(z<NE)? p.bada_e+z*AD3 : p.bada_s;
  else if(MODE==1) bias=(z<NE)? p.b1_e+z*HID : p.b1_s;
  else bias=(z<NE)? p.b2_e+z*D : p.b2_s;

  // A loader: thread tid owns A row (m0+tid)
  const __half* pA;
  uint32_t asz=16;
  if(MODE==0){
    int tok=(z<NE)? g_slot_tok[z*CAP+m0+tid] : (m0+tid);
    if(tok<0){ tok=0; asz=0; }
    pA=g_condh+(size_t)tok*DCND;
  } else {
    const __half* Ab=(MODE==1)? g_h : g_u;
    pA=Ab+(size_t)(base+m0+tid)*KD;
  }
  // B loader: thread tid owns N row (n0+tid) of [N][K] weights
  const __half* pB=Wt+(size_t)(n0+tid)*KD;

  uint32_t da0=sa+(uint32_t)tid*PADH*2;
  uint32_t db0=sb+(uint32_t)tid*PADH*2;

  // ldmatrix lane base addresses (buffer 0)
  uint32_t abase=sa+(uint32_t)(((wm*64+(tsel&1)*8+tr)*PADH+(tsel>>1)*8)*2);
  uint32_t bbase=sb+(uint32_t)(((wn*64+(tsel>>1)*8+tr)*PADH+(tsel&1)*8)*2);

  float acc[4][8][4];
  #pragma unroll
  for(int mt=0;mt<4;mt++)
    #pragma unroll
    for(int nt=0;nt<8;nt++)
      #pragma unroll
      for(int r=0;r<4;r++) acc[mt][nt][r]=0.f;

  auto issue=[&](int c,int buf){
    uint32_t da=da0+buf*BUF;
    const __half* srcA=pA+(size_t)c*KC;
    #pragma unroll
    for(int i=0;i<8;i++) cp16(da+i*16, srcA+i*8, asz);
    uint32_t db=db0+buf*BUF;
    const __half* srcB=pB+(size_t)c*KC;
    #pragma unroll
    for(int i=0;i<8;i++) cp16(db+i*16, srcB+i*8, 16u);
    asm volatile("cp.async.commit_group;" ::: "memory");
  };

  issue(0,0);
  for(int c=0;c<NC;c++){
    int cur=c&1;
    if(c+1<NC){
      issue(c+1,cur^1);
      asm volatile("cp.async.wait_group 1;" ::: "memory");
    } else {
      asm volatile("cp.async.wait_group 0;" ::: "memory");
    }
    __syncthreads();
    uint32_t ao=abase+cur*BUF;
    uint32_t bo=bbase+cur*BUF;
    #pragma unroll
    for(int kk=0;kk<4;kk++){                 // 4 x K16 per chunk
      uint32_t af[4][4], bf[4][4];
      #pragma unroll
      for(int mt=0;mt<4;mt++) ldsm4(af[mt], ao+(uint32_t)((mt*16*PADH)*2+kk*32));
      #pragma unroll
      for(int np=0;np<4;np++) ldsm4(bf[np], bo+(uint32_t)((np*16*PADH)*2+kk*32));
      #pragma unroll
      for(int mt=0;mt<4;mt++)
        #pragma unroll
        for(int np=0;np<4;np++){
          mma16(acc[mt][2*np+0], af[mt], &bf[np][0]);
          mma16(acc[mt][2*np+1], af[mt], &bf[np][2]);
        }
    }
    __syncthreads();
  }

  // ---- epilogue ----
  #pragma unroll
  for(int mt=0;mt<4;mt++){
    int r0=m0+wm*64+mt*16+g4;
    #pragma unroll
    for(int half=0;half<2;half++){
      int r=r0+half*8;
      if(MODE==0){
        size_t ro=(size_t)(base+r)*ND;
        #pragma unroll
        for(int nt=0;nt<8;nt++){
          int col=n0+wn*64+nt*8+t4*2;
          float2 o;
          o.x=acc[mt][nt][half*2+0]+bias[col+0];
          o.y=acc[mt][nt][half*2+1]+bias[col+1];
          *(float2*)(g_ada+ro+col)=o;
        }
      } else if(MODE==1){
        size_t ro=(size_t)(base+r)*ND;
        #pragma unroll
        for(int nt=0;nt<8;nt++){
          int col=n0+wn*64+nt*8+t4*2;
          float v0=gelu_tanh(acc[mt][nt][half*2+0]+bias[col+0]);
          float v1=gelu_tanh(acc[mt][nt][half*2+1]+bias[col+1]);
          __half2 hv=__floats2half2_rn(v0,v1);
          *(uint32_t*)(g_u+ro+col)=*(uint32_t*)&hv;
        }
      } else {
        const float* gp=&g_ada[(size_t)(base+r)*AD3+2*D];
        if(z<NE){
          int sidx=z*CAP+r;
          int tok=g_slot_tok[sidx];
          if(tok<0) continue;
          float f=g_slot_w[sidx]*p.mask[tok];
          float* mp=&g_moe[(size_t)tok*D];
          #pragma unroll
          for(int nt=0;nt<8;nt++){
            int col=n0+wn*64+nt*8+t4*2;
            atomicAdd(&mp[col+0],(acc[mt][nt][half*2+0]+bias[col+0])*gp[col+0]*f);
            atomicAdd(&mp[col+1],(acc[mt][nt][half*2+1]+bias[col+1])*gp[col+1]*f);
          }
        } else {
          float f=p.mask[r];
          float* sp=&g_sy[(size_t)r*D];
          #pragma unroll
          for(int nt=0;nt<8;nt++){
            int col=n0+wn*64+nt*8+t4*2;
            float2 o;
            o.x=(acc[mt][nt][half*2+0]+bias[col+0])*gp[col+0]*f;
            o.y=(acc[mt][nt][half*2+1]+bias[col+1])*gp[col+1]*f;
            *(float2*)(sp+col)=o;
          }
        }
      }
    }
  }
}

// ---------------- combine: out = (shared + 2*moe)/3 ----------------
__global__ void k_combine(float* __restrict__ out){
  size_t i=(size_t)blockIdx.x*blockDim.x+threadIdx.x;
  float4 s=((const float4*)g_sy)[i];
  float4 m=((const float4*)g_moe)[i];
  float4 o;
  const float inv3=1.f/3.f;
  o.x=(s.x+2.f*m.x)*inv3;
  o.y=(s.y+2.f*m.y)*inv3;
  o.z=(s.z+2.f*m.z)*inv3;
  o.w=(s.w+2.f*m.w)*inv3;
  ((float4*)out)[i]=o;
}

extern "C" void kernel_launch(void* const* d_in, const int* in_sizes, int n_in,
                              void* d_out, int out_size){
  P p;
  p.x     =(const float*)d_in[0];
  p.cond  =(const float*)d_in[1];
  p.mask  =(const float*)d_in[2];
  const float* Wg=(const float*)d_in[3];
  p.Wada_s=(const float*)d_in[4];
  p.bada_s=(const float*)d_in[5];
  p.W1_s  =(const float*)d_in[6];
  p.b1_s  =(const float*)d_in[7];
  p.W2_s  =(const float*)d_in[8];
  p.b2_s  =(const float*)d_in[9];
  p.Wada_e=(const float*)d_in[10];
  p.bada_e=(const float*)d_in[11];
  p.W1_e  =(const float*)d_in[12];
  p.b1_e  =(const float*)d_in[13];
  p.W2_e  =(const float*)d_in[14];
  p.b2_e  =(const float*)d_in[15];

  const int SMEM_SZ=4*128*PADH*2;   // 73728 B
  cudaFuncSetAttribute(k_gemm_mma<0>, cudaFuncAttributeMaxDynamicSharedMemorySize, SMEM_SZ);
  cudaFuncSetAttribute(k_gemm_mma<1>, cudaFuncAttributeMaxDynamicSharedMemorySize, SMEM_SZ);
  cudaFuncSetAttribute(k_gemm_mma<2>, cudaFuncAttributeMaxDynamicSharedMemorySize, SMEM_SZ);

  void *pslot=nullptr, *pmoe=nullptr, *pch=nullptr;
  cudaGetSymbolAddress(&pslot, g_slot_tok);
  cudaGetSymbolAddress(&pmoe,  g_moe);
  cudaGetSymbolAddress(&pch,   g_condh);
  cudaMemsetAsync(pslot, 0xFF, sizeof(int)*ROWS_R, 0);
  cudaMemsetAsync(pmoe,  0,    sizeof(float)*(size_t)T*D, 0);

  // fp16 cond; transpose+convert all weights to [N][K] fp16
  {
    size_t n4=(size_t)T*DCND/4;
    k_tohalf<<<(unsigned)((n4+255)/256),256>>>(p.cond,(__half*)pch,n4);
    dim3 b(32,8);
    dim3 ga(AD3/32, DCND/32, NE+1); k_wt<0><<<ga,b>>>(p);
    dim3 g1(HID/32, D/32,   NE+1);  k_wt<1><<<g1,b>>>(p);
    dim3 g2(D/32,   HID/32, NE+1);  k_wt<2><<<g2,b>>>(p);
  }

  k_router <<<T/4, 128>>>(p.x, Wg);
  k_hist   <<<NCHUNK, CHUNK>>>();
  k_scan   <<<1, 32>>>();
  k_place  <<<NCHUNK, CHUNK>>>();
  k_lnstats<<<T/4, 128>>>(p.x);

  dim3 g0(AD3/128, 64, NE+1);  k_gemm_mma<0><<<g0, 128, SMEM_SZ>>>(p);
  k_mod<<<ROWS_ALL, 256>>>(p.x);
  dim3 g1(HID/128, 64, NE+1);  k_gemm_mma<1><<<g1, 128, SMEM_SZ>>>(p);
  dim3 g2(D/128,   64, NE+1);  k_gemm_mma<2><<<g2, 128, SMEM_SZ>>>(p);

  k_combine<<<(T*D/4)/256, 256>>>((float*)d_out);
}

// round 6
// speedup vs baseline: 4.8684x; 1.1787x over previous
#include <cuda_runtime.h>
#include <cuda_fp16.h>
#include <math.h>
#include <stdint.h>

#define T 8192
#define D 1024
#define DCND 256
#define NE 8
#define HID 4096
#define CAP 2560
#define NTOK (T*2)
#define ROWS_R (NE*CAP)
#define ROWS_ALL (ROWS_R+T)
#define AD3 3072
#define NCHUNK 64
#define CHUNK 256
#define KC 64                 // K halves per chunk = 128B/row
#define PADH 72               // halves per smem row (64 + 8 pad) = 144B

// ---------------- scratch (device globals; no allocations) ----------------
__device__ int   g_tope[NTOK];
__device__ float g_topw[NTOK];
__device__ int   g_hist[NCHUNK*NE];
__device__ int   g_coff[NCHUNK*NE];
__device__ int   g_tpe[NE];
__device__ int   g_starts[NE];
__device__ int   g_ne[NE];
__device__ int   g_slot_tok[ROWS_R];
__device__ float g_slot_w[ROWS_R];
__device__ float g_mu[T];
__device__ float g_rstd[T];
__device__ float g_ada[(size_t)ROWS_ALL*AD3];    // shift|scale|gate (fp32)
__device__ __half g_h[(size_t)ROWS_ALL*D];       // modulated LN input (fp16)
__device__ __half g_u[(size_t)ROWS_ALL*HID];     // gelu(h@W1+b1) (fp16)
__device__ float g_moe[(size_t)T*D];
__device__ float g_sy[(size_t)T*D];
__device__ __half g_condh[(size_t)T*DCND];       // fp16 cond
// transposed [z][N][K] fp16 weights
__device__ __half g_wadat[(size_t)(NE+1)*AD3*DCND];
__device__ __half g_w1t[(size_t)(NE+1)*HID*D];
__device__ __half g_w2t[(size_t)(NE+1)*D*HID];

struct P {
  const float *x,*cond,*mask;
  const float *Wada_s,*bada_s,*W1_s,*b1_s,*W2_s,*b2_s;
  const float *Wada_e,*bada_e,*W1_e,*b1_e,*W2_e,*b2_e;
};

// ---------------- helpers ----------------
__device__ __forceinline__ uint32_t s2u(const void* p){
  uint32_t a;
  asm("{ .reg .u64 t; cvta.to.shared.u64 t, %1; cvt.u32.u64 %0, t; }" : "=r"(a) : "l"(p));
  return a;
}
__device__ __forceinline__ void cp16(uint32_t d, const void* s, uint32_t sz){
  asm volatile("cp.async.cg.shared.global [%0], [%1], 16, %2;" :: "r"(d),"l"(s),"r"(sz) : "memory");
}
__device__ __forceinline__ void mma16(float* c, const uint32_t* a, const uint32_t* b){
  asm volatile("mma.sync.aligned.m16n8k16.row.col.f32.f16.f16.f32 "
    "{%0,%1,%2,%3}, {%4,%5,%6,%7}, {%8,%9}, {%0,%1,%2,%3};"
    : "+f"(c[0]),"+f"(c[1]),"+f"(c[2]),"+f"(c[3])
    : "r"(a[0]),"r"(a[1]),"r"(a[2]),"r"(a[3]), "r"(b[0]),"r"(b[1]));
}
__device__ __forceinline__ void ldsm4(uint32_t* r, uint32_t a){
  asm volatile("ldmatrix.sync.aligned.m8n8.x4.shared.b16 {%0,%1,%2,%3}, [%4];"
    : "=r"(r[0]),"=r"(r[1]),"=r"(r[2]),"=r"(r[3]) : "r"(a));
}

// ---------------- f32 -> f16 copy (cond) ----------------
__global__ void k_tohalf(const float* __restrict__ s, __half* __restrict__ d, size_t n4){
  size_t i=(size_t)blockIdx.x*blockDim.x+threadIdx.x;
  if(i>=n4) return;
  float4 v=((const float4*)s)[i];
  __half2 lo=__floats2half2_rn(v.x,v.y);
  __half2 hi=__floats2half2_rn(v.z,v.w);
  uint2 o; o.x=*(uint32_t*)&lo; o.y=*(uint32_t*)&hi;
  ((uint2*)d)[i]=o;
}

// ---------------- weight transpose [K,N]->[N,K] fp16 ----------------
template<int MODE>
__global__ void k_wt(P p){
  constexpr int KD=(MODE==0)?DCND:(MODE==1)?D:HID;
  constexpr int ND=(MODE==0)?AD3:(MODE==1)?HID:D;
  int z=blockIdx.z;
  const float* W;
  if(MODE==0) W=(z<NE)? p.Wada_e+(size_t)z*KD*ND : p.Wada_s;
  else if(MODE==1) W=(z<NE)? p.W1_e+(size_t)z*KD*ND : p.W1_s;
  else W=(z<NE)? p.W2_e+(size_t)z*KD*ND : p.W2_s;
  __half* Wt=((MODE==0)? g_wadat : (MODE==1)? g_w1t : g_w2t)+(size_t)z*KD*ND;
  __shared__ float t[32][33];
  int n0=blockIdx.x*32, k0=blockIdx.y*32;
  int tx=threadIdx.x, ty=threadIdx.y;
  #pragma unroll
  for(int i=0;i<32;i+=8)
    t[ty+i][tx]=W[(size_t)(k0+ty+i)*ND+n0+tx];
  __syncthreads();
  #pragma unroll
  for(int i=0;i<32;i+=8)
    Wt[(size_t)(n0+ty+i)*KD+k0+tx]=__float2half_rn(t[tx][ty+i]);
}

// ---------------- router: warp/token, top-2 of 7 ----------------
__global__ void k_router(const float* __restrict__ x, const float* __restrict__ Wg){
  int w=(blockIdx.x*blockDim.x+threadIdx.x)>>5;
  int lane=threadIdx.x&31;
  if(w>=T) return;
  const float* xr=x+(size_t)w*D;
  float a[7]={0.f,0.f,0.f,0.f,0.f,0.f,0.f};
  for(int k=lane;k<D;k+=32){
    float xv=xr[k];
    #pragma unroll
    for(int j=0;j<7;j++) a[j]+=xv*Wg[k*7+j];
  }
  #pragma unroll
  for(int j=0;j<7;j++)
    for(int o=16;o;o>>=1) a[j]+=__shfl_xor_sync(0xffffffffu,a[j],o);
  if(lane==0){
    int j0=0;
    #pragma unroll
    for(int j=1;j<7;j++) if(a[j]>a[j0]) j0=j;
    int j1=-1;
    #pragma unroll
    for(int j=0;j<7;j++){ if(j==j0) continue; if(j1<0||a[j]>a[j1]) j1=j; }
    float e1=expf(a[j1]-a[j0]);
    float inv=1.f/(1.f+e1);
    g_tope[2*w]=j0;   g_topw[2*w]=inv;
    g_tope[2*w+1]=j1; g_topw[2*w+1]=e1*inv;
  }
}

// ---------------- stable counting sort by expert ----------------
__global__ void k_hist(){
  __shared__ int cnt[NE];
  int tid=threadIdx.x;
  if(tid<NE) cnt[tid]=0;
  __syncthreads();
  atomicAdd(&cnt[g_tope[blockIdx.x*CHUNK+tid]],1);
  __syncthreads();
  if(tid<NE) g_hist[blockIdx.x*NE+tid]=cnt[tid];
}
__global__ void k_scan(){
  int tid=threadIdx.x;
  __shared__ int tpe[NE], st[NE];
  if(tid<NE){
    int s=0;
    for(int c=0;c<NCHUNK;c++) s+=g_hist[c*NE+tid];
    tpe[tid]=s; g_tpe[tid]=s; g_ne[tid]=s<CAP?s:CAP;
  }
  __syncthreads();
  if(tid==0){
    int cum=0;
    for(int e=0;e<NE;e++){ st[e]=cum; g_starts[e]=cum; cum+=tpe[e]; }
  }
  __syncthreads();
  if(tid<NE){
    int run=st[tid];
    for(int c=0;c<NCHUNK;c++){ g_coff[c*NE+tid]=run; run+=g_hist[c*NE+tid]; }
  }
}
__global__ void k_place(){
  __shared__ int se[CHUNK];
  int tid=threadIdx.x;
  int g=blockIdx.x*CHUNK+tid;
  int e=g_tope[g];
  se[tid]=e;
  __syncthreads();
  int rank=0;
  for(int j=0;j<tid;j++) rank += (se[j]==e);
  int pos=g_coff[blockIdx.x*NE+e]+rank;
  int slot=pos-g_starts[e];
  if(slot<CAP){
    g_slot_tok[e*CAP+slot]=g>>1;
    g_slot_w[e*CAP+slot]=g_topw[g];
  }
}

// ---------------- LN stats ----------------
__global__ void k_lnstats(const float* __restrict__ x){
  int w=(blockIdx.x*blockDim.x+threadIdx.x)>>5;
  int lane=threadIdx.x&31;
  if(w>=T) return;
  const float* xr=x+(size_t)w*D;
  float s=0.f,s2=0.f;
  for(int k=lane;k<D;k+=32){ float v=xr[k]; s+=v; s2+=v*v; }
  for(int o=16;o;o>>=1){
    s+=__shfl_xor_sync(0xffffffffu,s,o);
    s2+=__shfl_xor_sync(0xffffffffu,s2,o);
  }
  if(lane==0){
    float mu=s*(1.f/(float)D);
    float var=s2*(1.f/(float)D)-mu*mu;
    g_mu[w]=mu;
    g_rstd[w]=rsqrtf(var+1e-5f);
  }
}

// ---------------- modulate: h = f16( LN(x)*(1+scale)+shift ) ----------------
__global__ void k_mod(const float* __restrict__ x){
  int r=blockIdx.x;
  int tok=(r<ROWS_R)? g_slot_tok[r] : (r-ROWS_R);
  int d4=threadIdx.x;
  uint2* hp=(uint2*)(g_h+(size_t)r*D);
  if(tok<0){ uint2 zz; zz.x=0u; zz.y=0u; hp[d4]=zz; return; }
  const float4* xp=(const float4*)(x+(size_t)tok*D);
  float mu=g_mu[tok], rs=g_rstd[tok];
  const float* ada=g_ada+(size_t)r*AD3;
  float4 xv=xp[d4];
  float4 sh=((const float4*)ada)[d4];
  float4 sc=((const float4*)(ada+D))[d4];
  float h0=(xv.x-mu)*rs*(1.f+sc.x)+sh.x;
  float h1=(xv.y-mu)*rs*(1.f+sc.y)+sh.y;
  float h2=(xv.z-mu)*rs*(1.f+sc.z)+sh.z;
  float h3=(xv.w-mu)*rs*(1.f+sc.w)+sh.w;
  __half2 lo=__floats2half2_rn(h0,h1);
  __half2 hi=__floats2half2_rn(h2,h3);
  uint2 o; o.x=*(uint32_t*)&lo; o.y=*(uint32_t*)&hi;
  hp[d4]=o;
}

__device__ __forceinline__ float gelu_tanh(float v){
  const float c=0.7978845608028654f;
  return 0.5f*v*(1.f+tanhf(c*(v+0.044715f*v*v*v)));
}

// ---------------- fp16 mma.sync GEMM, 128x128 tile, 256 threads, warp tile 32x64 ----------------
// MODE 0: ada = gather(condh) @ Wada + bada             (K=256,  N=3072)
// MODE 1: u   = f16(gelu(g_h @ W1 + b1))                (K=1024, N=4096)
// MODE 2: y   = g_u @ W2 + b2 -> gate*mask*w scatter    (K=4096, N=1024)
template<int MODE>
__global__ void __launch_bounds__(256,2) k_gemm_mma(P p){
  constexpr int KD=(MODE==0)?DCND:(MODE==1)?D:HID;
  constexpr int ND=(MODE==0)?AD3:(MODE==1)?HID:D;
  constexpr int NC=KD/KC;
  constexpr uint32_t BUF=128*PADH*2;    // 18432 B per stage per operand

  int z=blockIdx.z;
  int Mz=(z<NE)? g_ne[z] : T;
  int m0=blockIdx.y*128;
  if(m0>=Mz) return;
  int n0=blockIdx.x*128;
  int base=(z<NE)? z*CAP : ROWS_R;

  extern __shared__ __half smh[];
  uint32_t sa=s2u(smh);
  uint32_t sb=sa+2*BUF;

  int tid=threadIdx.x, warp=tid>>5, lane=tid&31;
  int wm=warp>>1, wn=warp&1;          // wm 0..3 (32-row strips), wn 0..1 (64-col strips)
  int g4=lane>>2, t4=lane&3;
  int tsel=lane>>3, tr=lane&7;

  const __half* Wt=((MODE==0)? g_wadat : (MODE==1)? g_w1t : g_w2t)+(size_t)z*(size_t)KD*ND;
  const float* bias;
  if(MODE==0) bias=(z<NE)? p.bada_e+z*AD3 : p.bada_s;
  else if(MODE==1) bias=(z<NE)? p.b1_e+z*HID : p.b1_s;
  else bias=(z<NE)? p.b2_e+z*D : p.b2_s;

  // loaders: 256 threads, thread owns row (tid>>1), half-row segment (tid&1)
  int lrow=tid>>1, lseg=tid&1;
  const __half* pA;
  uint32_t asz=16;
  if(MODE==0){
    int tok=(z<NE)? g_slot_tok[z*CAP+m0+lrow] : (m0+lrow);
    if(tok<0){ tok=0; asz=0; }
    pA=g_condh+(size_t)tok*DCND+lseg*32;
  } else {
    const __half* Ab=(MODE==1)? g_h : g_u;
    pA=Ab+(size_t)(base+m0+lrow)*KD+lseg*32;
  }
  const __half* pB=Wt+(size_t)(n0+lrow)*KD+lseg*32;

  uint32_t da0=sa+(uint32_t)(lrow*PADH+lseg*32)*2;
  uint32_t db0=sb+(uint32_t)(lrow*PADH+lseg*32)*2;

  // ldmatrix lane base addresses (buffer 0)
  uint32_t abase=sa+(uint32_t)(((wm*32+(tsel&1)*8+tr)*PADH+(tsel>>1)*8)*2);
  uint32_t bbase=sb+(uint32_t)(((wn*64+(tsel>>1)*8+tr)*PADH+(tsel&1)*8)*2);

  float acc[2][8][4];
  #pragma unroll
  for(int mt=0;mt<2;mt++)
    #pragma unroll
    for(int nt=0;nt<8;nt++)
      #pragma unroll
      for(int r=0;r<4;r++) acc[mt][nt][r]=0.f;

  auto issue=[&](int c,int buf){
    uint32_t da=da0+buf*BUF;
    const __half* srcA=pA+(size_t)c*KC;
    #pragma unroll
    for(int i=0;i<4;i++) cp16(da+i*16, srcA+i*8, asz);
    uint32_t db=db0+buf*BUF;
    const __half* srcB=pB+(size_t)c*KC;
    #pragma unroll
    for(int i=0;i<4;i++) cp16(db+i*16, srcB+i*8, 16u);
    asm volatile("cp.async.commit_group;" ::: "memory");
  };

  issue(0,0);
  for(int c=0;c<NC;c++){
    int cur=c&1;
    if(c+1<NC){
      issue(c+1,cur^1);
      asm volatile("cp.async.wait_group 1;" ::: "memory");
    } else {
      asm volatile("cp.async.wait_group 0;" ::: "memory");
    }
    __syncthreads();
    uint32_t ao=abase+cur*BUF;
    uint32_t bo=bbase+cur*BUF;
    #pragma unroll
    for(int kk=0;kk<4;kk++){                 // 4 x K16 per chunk
      uint32_t af[2][4], bf[4][4];
      #pragma unroll
      for(int mt=0;mt<2;mt++) ldsm4(af[mt], ao+(uint32_t)((mt*16*PADH)*2+kk*32));
      #pragma unroll
      for(int np=0;np<4;np++) ldsm4(bf[np], bo+(uint32_t)((np*16*PADH)*2+kk*32));
      #pragma unroll
      for(int mt=0;mt<2;mt++)
        #pragma unroll
        for(int np=0;np<4;np++){
          mma16(acc[mt][2*np+0], af[mt], &bf[np][0]);
          mma16(acc[mt][2*np+1], af[mt], &bf[np][2]);
        }
    }
    __syncthreads();
  }

  // ---- epilogue ----
  #pragma unroll
  for(int mt=0;mt<2;mt++){
    int r0=m0+wm*32+mt*16+g4;
    #pragma unroll
    for(int half=0;half<2;half++){
      int r=r0+half*8;
      if(MODE==0){
        size_t ro=(size_t)(base+r)*ND;
        #pragma unroll
        for(int nt=0;nt<8;nt++){
          int col=n0+wn*64+nt*8+t4*2;
          float2 o;
          o.x=acc[mt][nt][half*2+0]+bias[col+0];
          o.y=acc[mt][nt][half*2+1]+bias[col+1];
          *(float2*)(g_ada+ro+col)=o;
        }
      } else if(MODE==1){
        size_t ro=(size_t)(base+r)*ND;
        #pragma unroll
        for(int nt=0;nt<8;nt++){
          int col=n0+wn*64+nt*8+t4*2;
          float v0=gelu_tanh(acc[mt][nt][half*2+0]+bias[col+0]);
          float v1=gelu_tanh(acc[mt][nt][half*2+1]+bias[col+1]);
          __half2 hv=__floats2half2_rn(v0,v1);
          *(uint32_t*)(g_u+ro+col)=*(uint32_t*)&hv;
        }
      } else {
        const float* gp=&g_ada[(size_t)(base+r)*AD3+2*D];
        if(z<NE){
          int sidx=z*CAP+r;
          int tok=g_slot_tok[sidx];
          if(tok<0) continue;
          float f=g_slot_w[sidx]*p.mask[tok];
          float* mp=&g_moe[(size_t)tok*D];
          #pragma unroll
          for(int nt=0;nt<8;nt++){
            int col=n0+wn*64+nt*8+t4*2;
            atomicAdd(&mp[col+0],(acc[mt][nt][half*2+0]+bias[col+0])*gp[col+0]*f);
            atomicAdd(&mp[col+1],(acc[mt][nt][half*2+1]+bias[col+1])*gp[col+1]*f);
          }
        } else {
          float f=p.mask[r];
          float* sp=&g_sy[(size_t)r*D];
          #pragma unroll
          for(int nt=0;nt<8;nt++){
            int col=n0+wn*64+nt*8+t4*2;
            float2 o;
            o.x=(acc[mt][nt][half*2+0]+bias[col+0])*gp[col+0]*f;
            o.y=(acc[mt][nt][half*2+1]+bias[col+1])*gp[col+1]*f;
            *(float2*)(sp+col)=o;
          }
        }
      }
    }
  }
}

// ---------------- combine: out = (shared + 2*moe)/3 ----------------
__global__ void k_combine(float* __restrict__ out){
  size_t i=(size_t)blockIdx.x*blockDim.x+threadIdx.x;
  float4 s=((const float4*)g_sy)[i];
  float4 m=((const float4*)g_moe)[i];
  float4 o;
  const float inv3=1.f/3.f;
  o.x=(s.x+2.f*m.x)*inv3;
  o.y=(s.y+2.f*m.y)*inv3;
  o.z=(s.z+2.f*m.z)*inv3;
  o.w=(s.w+2.f*m.w)*inv3;
  ((float4*)out)[i]=o;
}

extern "C" void kernel_launch(void* const* d_in, const int* in_sizes, int n_in,
                              void* d_out, int out_size){
  P p;
  p.x     =(const float*)d_in[0];
  p.cond  =(const float*)d_in[1];
  p.mask  =(const float*)d_in[2];
  const float* Wg=(const float*)d_in[3];
  p.Wada_s=(const float*)d_in[4];
  p.bada_s=(const float*)d_in[5];
  p.W1_s  =(const float*)d_in[6];
  p.b1_s  =(const float*)d_in[7];
  p.W2_s  =(const float*)d_in[8];
  p.b2_s  =(const float*)d_in[9];
  p.Wada_e=(const float*)d_in[10];
  p.bada_e=(const float*)d_in[11];
  p.W1_e  =(const float*)d_in[12];
  p.b1_e  =(const float*)d_in[13];
  p.W2_e  =(const float*)d_in[14];
  p.b2_e  =(const float*)d_in[15];

  const int SMEM_SZ=4*128*PADH*2;   // 73728 B
  cudaFuncSetAttribute(k_gemm_mma<0>, cudaFuncAttributeMaxDynamicSharedMemorySize, SMEM_SZ);
  cudaFuncSetAttribute(k_gemm_mma<1>, cudaFuncAttributeMaxDynamicSharedMemorySize, SMEM_SZ);
  cudaFuncSetAttribute(k_gemm_mma<2>, cudaFuncAttributeMaxDynamicSharedMemorySize, SMEM_SZ);

  void *pslot=nullptr, *pmoe=nullptr, *pch=nullptr;
  cudaGetSymbolAddress(&pslot, g_slot_tok);
  cudaGetSymbolAddress(&pmoe,  g_moe);
  cudaGetSymbolAddress(&pch,   g_condh);
  cudaMemsetAsync(pslot, 0xFF, sizeof(int)*ROWS_R, 0);
  cudaMemsetAsync(pmoe,  0,    sizeof(float)*(size_t)T*D, 0);

  // fp16 cond; transpose+convert all weights to [N][K] fp16
  {
    size_t n4=(size_t)T*DCND/4;
    k_tohalf<<<(unsigned)((n4+255)/256),256>>>(p.cond,(__half*)pch,n4);
    dim3 b(32,8);
    dim3 ga(AD3/32, DCND/32, NE+1); k_wt<0><<<ga,b>>>(p);
    dim3 g1(HID/32, D/32,   NE+1);  k_wt<1><<<g1,b>>>(p);
    dim3 g2(D/32,   HID/32, NE+1);  k_wt<2><<<g2,b>>>(p);
  }

  k_router <<<T/4, 128>>>(p.x, Wg);
  k_hist   <<<NCHUNK, CHUNK>>>();
  k_scan   <<<1, 32>>>();
  k_place  <<<NCHUNK, CHUNK>>>();
  k_lnstats<<<T/4, 128>>>(p.x);

  dim3 g0(AD3/128, 64, NE+1);  k_gemm_mma<0><<<g0, 256, SMEM_SZ>>>(p);
  k_mod<<<ROWS_ALL, 256>>>(p.x);
  dim3 g1(HID/128, 64, NE+1);  k_gemm_mma<1><<<g1, 256, SMEM_SZ>>>(p);
  dim3 g2(D/128,   64, NE+1);  k_gemm_mma<2><<<g2, 256, SMEM_SZ>>>(p);

  k_combine<<<(T*D/4)/256, 256>>>((float*)d_out);
}

// round 7
// speedup vs baseline: 5.2752x; 1.0836x over previous
#include <cuda_runtime.h>
#include <cuda_fp16.h>
#include <math.h>
#include <stdint.h>

#define T 8192
#define D 1024
#define DCND 256
#define NE 8
#define HID 4096
#define CAP 2560
#define NTOK (T*2)
#define ROWS_R (NE*CAP)
#define ROWS_ALL (ROWS_R+T)
#define AD3 3072
#define NCHUNK 64
#define CHUNK 256
#define KC 64                 // K halves per chunk = 128B/row
#define PADH 72               // halves per smem row (64 + 8 pad) = 144B

// ---------------- scratch (device globals; no allocations) ----------------
__device__ int   g_tope[NTOK];
__device__ float g_topw[NTOK];
__device__ int   g_hist[NCHUNK*NE];
__device__ int   g_coff[NCHUNK*NE];
__device__ int   g_tpe[NE];
__device__ int   g_starts[NE];
__device__ int   g_ne[NE];
__device__ int   g_slot_tok[ROWS_R];
__device__ float g_slot_w[ROWS_R];
__device__ float g_mu[T];
__device__ float g_rstd[T];
__device__ __half g_ada[(size_t)ROWS_ALL*AD3];   // shift|scale|gate (fp16)
__device__ __half g_h[(size_t)ROWS_ALL*D];       // modulated LN input (fp16)
__device__ __half g_u[(size_t)ROWS_ALL*HID];     // gelu(h@W1+b1) (fp16)
__device__ __half g_condh[(size_t)T*DCND];       // fp16 cond
// transposed [z][N][K] fp16 weights
__device__ __half g_wadat[(size_t)(NE+1)*AD3*DCND];
__device__ __half g_w1t[(size_t)(NE+1)*HID*D];
__device__ __half g_w2t[(size_t)(NE+1)*D*HID];

struct P {
  const float *x,*cond,*mask;
  const float *Wada_s,*bada_s,*W1_s,*b1_s,*W2_s,*b2_s;
  const float *Wada_e,*bada_e,*W1_e,*b1_e,*W2_e,*b2_e;
  float *out;
};

// ---------------- helpers ----------------
__device__ __forceinline__ uint32_t s2u(const void* p){
  uint32_t a;
  asm("{ .reg .u64 t; cvta.to.shared.u64 t, %1; cvt.u32.u64 %0, t; }" : "=r"(a) : "l"(p));
  return a;
}
__device__ __forceinline__ void cp16(uint32_t d, const void* s, uint32_t sz){
  asm volatile("cp.async.cg.shared.global [%0], [%1], 16, %2;" :: "r"(d),"l"(s),"r"(sz) : "memory");
}
__device__ __forceinline__ void mma16(float* c, const uint32_t* a, const uint32_t* b){
  asm volatile("mma.sync.aligned.m16n8k16.row.col.f32.f16.f16.f32 "
    "{%0,%1,%2,%3}, {%4,%5,%6,%7}, {%8,%9}, {%0,%1,%2,%3};"
    : "+f"(c[0]),"+f"(c[1]),"+f"(c[2]),"+f"(c[3])
    : "r"(a[0]),"r"(a[1]),"r"(a[2]),"r"(a[3]), "r"(b[0]),"r"(b[1]));
}
__device__ __forceinline__ void ldsm4(uint32_t* r, uint32_t a){
  asm volatile("ldmatrix.sync.aligned.m8n8.x4.shared.b16 {%0,%1,%2,%3}, [%4];"
    : "=r"(r[0]),"=r"(r[1]),"=r"(r[2]),"=r"(r[3]) : "r"(a));
}

// ---------------- f32 -> f16 copy (cond) ----------------
__global__ void k_tohalf(const float* __restrict__ s, __half* __restrict__ d, size_t n4){
  size_t i=(size_t)blockIdx.x*blockDim.x+threadIdx.x;
  if(i>=n4) return;
  float4 v=((const float4*)s)[i];
  __half2 lo=__floats2half2_rn(v.x,v.y);
  __half2 hi=__floats2half2_rn(v.z,v.w);
  uint2 o; o.x=*(uint32_t*)&lo; o.y=*(uint32_t*)&hi;
  ((uint2*)d)[i]=o;
}

// ---------------- weight transpose [K,N]->[N,K] fp16 ----------------
template<int MODE>
__global__ void k_wt(P p){
  constexpr int KD=(MODE==0)?DCND:(MODE==1)?D:HID;
  constexpr int ND=(MODE==0)?AD3:(MODE==1)?HID:D;
  int z=blockIdx.z;
  const float* W;
  if(MODE==0) W=(z<NE)? p.Wada_e+(size_t)z*KD*ND : p.Wada_s;
  else if(MODE==1) W=(z<NE)? p.W1_e+(size_t)z*KD*ND : p.W1_s;
  else W=(z<NE)? p.W2_e+(size_t)z*KD*ND : p.W2_s;
  __half* Wt=((MODE==0)? g_wadat : (MODE==1)? g_w1t : g_w2t)+(size_t)z*KD*ND;
  __shared__ float t[32][33];
  int n0=blockIdx.x*32, k0=blockIdx.y*32;
  int tx=threadIdx.x, ty=threadIdx.y;
  #pragma unroll
  for(int i=0;i<32;i+=8)
    t[ty+i][tx]=W[(size_t)(k0+ty+i)*ND+n0+tx];
  __syncthreads();
  #pragma unroll
  for(int i=0;i<32;i+=8)
    Wt[(size_t)(n0+ty+i)*KD+k0+tx]=__float2half_rn(t[tx][ty+i]);
}

// ---------------- router: warp/token, top-2 of 7 ----------------
__global__ void k_router(const float* __restrict__ x, const float* __restrict__ Wg){
  int w=(blockIdx.x*blockDim.x+threadIdx.x)>>5;
  int lane=threadIdx.x&31;
  if(w>=T) return;
  const float* xr=x+(size_t)w*D;
  float a[7]={0.f,0.f,0.f,0.f,0.f,0.f,0.f};
  for(int k=lane;k<D;k+=32){
    float xv=xr[k];
    #pragma unroll
    for(int j=0;j<7;j++) a[j]+=xv*Wg[k*7+j];
  }
  #pragma unroll
  for(int j=0;j<7;j++)
    for(int o=16;o;o>>=1) a[j]+=__shfl_xor_sync(0xffffffffu,a[j],o);
  if(lane==0){
    int j0=0;
    #pragma unroll
    for(int j=1;j<7;j++) if(a[j]>a[j0]) j0=j;
    int j1=-1;
    #pragma unroll
    for(int j=0;j<7;j++){ if(j==j0) continue; if(j1<0||a[j]>a[j1]) j1=j; }
    float e1=expf(a[j1]-a[j0]);
    float inv=1.f/(1.f+e1);
    g_tope[2*w]=j0;   g_topw[2*w]=inv;
    g_tope[2*w+1]=j1; g_topw[2*w+1]=e1*inv;
  }
}

// ---------------- stable counting sort by expert ----------------
__global__ void k_hist(){
  __shared__ int cnt[NE];
  int tid=threadIdx.x;
  if(tid<NE) cnt[tid]=0;
  __syncthreads();
  atomicAdd(&cnt[g_tope[blockIdx.x*CHUNK+tid]],1);
  __syncthreads();
  if(tid<NE) g_hist[blockIdx.x*NE+tid]=cnt[tid];
}
__global__ void k_scan(){
  int tid=threadIdx.x;
  __shared__ int tpe[NE], st[NE];
  if(tid<NE){
    int s=0;
    for(int c=0;c<NCHUNK;c++) s+=g_hist[c*NE+tid];
    tpe[tid]=s; g_tpe[tid]=s; g_ne[tid]=s<CAP?s:CAP;
  }
  __syncthreads();
  if(tid==0){
    int cum=0;
    for(int e=0;e<NE;e++){ st[e]=cum; g_starts[e]=cum; cum+=tpe[e]; }
  }
  __syncthreads();
  if(tid<NE){
    int run=st[tid];
    for(int c=0;c<NCHUNK;c++){ g_coff[c*NE+tid]=run; run+=g_hist[c*NE+tid]; }
  }
}
__global__ void k_place(){
  __shared__ int se[CHUNK];
  int tid=threadIdx.x;
  int g=blockIdx.x*CHUNK+tid;
  int e=g_tope[g];
  se[tid]=e;
  __syncthreads();
  int rank=0;
  for(int j=0;j<tid;j++) rank += (se[j]==e);
  int pos=g_coff[blockIdx.x*NE+e]+rank;
  int slot=pos-g_starts[e];
  if(slot<CAP){
    g_slot_tok[e*CAP+slot]=g>>1;
    g_slot_w[e*CAP+slot]=g_topw[g];
  }
}

// ---------------- LN stats ----------------
__global__ void k_lnstats(const float* __restrict__ x){
  int w=(blockIdx.x*blockDim.x+threadIdx.x)>>5;
  int lane=threadIdx.x&31;
  if(w>=T) return;
  const float* xr=x+(size_t)w*D;
  float s=0.f,s2=0.f;
  for(int k=lane;k<D;k+=32){ float v=xr[k]; s+=v; s2+=v*v; }
  for(int o=16;o;o>>=1){
    s+=__shfl_xor_sync(0xffffffffu,s,o);
    s2+=__shfl_xor_sync(0xffffffffu,s2,o);
  }
  if(lane==0){
    float mu=s*(1.f/(float)D);
    float var=s2*(1.f/(float)D)-mu*mu;
    g_mu[w]=mu;
    g_rstd[w]=rsqrtf(var+1e-5f);
  }
}

// ---------------- modulate: h = f16( LN(x)*(1+scale)+shift ) ----------------
__global__ void k_mod(const float* __restrict__ x){
  int r=blockIdx.x;
  int tok=(r<ROWS_R)? g_slot_tok[r] : (r-ROWS_R);
  int d4=threadIdx.x;
  uint2* hp=(uint2*)(g_h+(size_t)r*D);
  if(tok<0){ uint2 zz; zz.x=0u; zz.y=0u; hp[d4]=zz; return; }
  const float4* xp=(const float4*)(x+(size_t)tok*D);
  float mu=g_mu[tok], rs=g_rstd[tok];
  const __half* ada=g_ada+(size_t)r*AD3;
  float4 xv=xp[d4];
  uint2 shu=((const uint2*)ada)[d4];
  uint2 scu=((const uint2*)(ada+D))[d4];
  float2 sh0=__half22float2(*(__half2*)&shu.x);
  float2 sh1=__half22float2(*(__half2*)&shu.y);
  float2 sc0=__half22float2(*(__half2*)&scu.x);
  float2 sc1=__half22float2(*(__half2*)&scu.y);
  float h0=(xv.x-mu)*rs*(1.f+sc0.x)+sh0.x;
  float h1=(xv.y-mu)*rs*(1.f+sc0.y)+sh0.y;
  float h2=(xv.z-mu)*rs*(1.f+sc1.x)+sh1.x;
  float h3=(xv.w-mu)*rs*(1.f+sc1.y)+sh1.y;
  __half2 lo=__floats2half2_rn(h0,h1);
  __half2 hi=__floats2half2_rn(h2,h3);
  uint2 o; o.x=*(uint32_t*)&lo; o.y=*(uint32_t*)&hi;
  hp[d4]=o;
}

__device__ __forceinline__ float gelu_tanh(float v){
  const float c=0.7978845608028654f;
  return 0.5f*v*(1.f+tanhf(c*(v+0.044715f*v*v*v)));
}

// ---------------- fp16 mma.sync GEMM, 128x128 tile, 256 thr, 3-stage cp.async ----------------
// MODE 0: ada = f16(gather(condh) @ Wada + bada)        (K=256,  N=3072)
// MODE 1: u   = f16(gelu(g_h @ W1 + b1))                (K=1024, N=4096)
// MODE 2: y   = g_u @ W2 + b2 -> gate*mask*w atomic out (K=4096, N=1024)
template<int MODE>
__global__ void __launch_bounds__(256,2) k_gemm_mma(P p){
  constexpr int KD=(MODE==0)?DCND:(MODE==1)?D:HID;
  constexpr int ND=(MODE==0)?AD3:(MODE==1)?HID:D;
  constexpr int NC=KD/KC;
  constexpr uint32_t BUF=128*PADH*2;    // 18432 B per stage per operand

  int z=blockIdx.z;
  int Mz=(z<NE)? g_ne[z] : T;
  int m0=blockIdx.y*128;
  if(m0>=Mz) return;
  int n0=blockIdx.x*128;
  int base=(z<NE)? z*CAP : ROWS_R;

  extern __shared__ __half smh[];
  uint32_t sa=s2u(smh);        // A: 3 stages
  uint32_t sb=sa+3*BUF;        // B: 3 stages

  int tid=threadIdx.x, warp=tid>>5, lane=tid&31;
  int wm=warp>>1, wn=warp&1;
  int g4=lane>>2, t4=lane&3;
  int tsel=lane>>3, tr=lane&7;

  const __half* Wt=((MODE==0)? g_wadat : (MODE==1)? g_w1t : g_w2t)+(size_t)z*(size_t)KD*ND;
  const float* bias;
  if(MODE==0) bias=(z<NE)? p.bada_e+z*AD3 : p.bada_s;
  else if(MODE==1) bias=(z<NE)? p.b1_e+z*HID : p.b1_s;
  else bias=(z<NE)? p.b2_e+z*D : p.b2_s;

  // loaders: thread owns row (tid>>1), half-row segment (tid&1)
  int lrow=tid>>1, lseg=tid&1;
  const __half* pA;
  uint32_t asz=16;
  if(MODE==0){
    int tok=(z<NE)? g_slot_tok[z*CAP+m0+lrow] : (m0+lrow);
    if(tok<0){ tok=0; asz=0; }
    pA=g_condh+(size_t)tok*DCND+lseg*32;
  } else {
    const __half* Ab=(MODE==1)? g_h : g_u;
    pA=Ab+(size_t)(base+m0+lrow)*KD+lseg*32;
  }
  const __half* pB=Wt+(size_t)(n0+lrow)*KD+lseg*32;

  uint32_t da0=sa+(uint32_t)(lrow*PADH+lseg*32)*2;
  uint32_t db0=sb+(uint32_t)(lrow*PADH+lseg*32)*2;

  uint32_t abase=sa+(uint32_t)(((wm*32+(tsel&1)*8+tr)*PADH+(tsel>>1)*8)*2);
  uint32_t bbase=sb+(uint32_t)(((wn*64+(tsel>>1)*8+tr)*PADH+(tsel&1)*8)*2);

  float acc[2][8][4];
  #pragma unroll
  for(int mt=0;mt<2;mt++)
    #pragma unroll
    for(int nt=0;nt<8;nt++)
      #pragma unroll
      for(int r=0;r<4;r++) acc[mt][nt][r]=0.f;

  auto issue=[&](int c,int buf){
    uint32_t da=da0+buf*BUF;
    const __half* srcA=pA+(size_t)c*KC;
    #pragma unroll
    for(int i=0;i<4;i++) cp16(da+i*16, srcA+i*8, asz);
    uint32_t db=db0+buf*BUF;
    const __half* srcB=pB+(size_t)c*KC;
    #pragma unroll
    for(int i=0;i<4;i++) cp16(db+i*16, srcB+i*8, 16u);
    asm volatile("cp.async.commit_group;" ::: "memory");
  };

  issue(0,0);
  if(NC>1) issue(1,1);
  int buf=0;
  for(int c=0;c<NC;c++){
    if(c+1<NC) asm volatile("cp.async.wait_group 1;" ::: "memory");
    else       asm volatile("cp.async.wait_group 0;" ::: "memory");
    __syncthreads();
    uint32_t ao=abase+buf*BUF;
    uint32_t bo=bbase+buf*BUF;
    #pragma unroll
    for(int kk=0;kk<4;kk++){                 // 4 x K16 per chunk
      uint32_t af[2][4], bf[4][4];
      #pragma unroll
      for(int mt=0;mt<2;mt++) ldsm4(af[mt], ao+(uint32_t)((mt*16*PADH)*2+kk*32));
      #pragma unroll
      for(int np=0;np<4;np++) ldsm4(bf[np], bo+(uint32_t)((np*16*PADH)*2+kk*32));
      #pragma unroll
      for(int mt=0;mt<2;mt++)
        #pragma unroll
        for(int np=0;np<4;np++){
          mma16(acc[mt][2*np+0], af[mt], &bf[np][0]);
          mma16(acc[mt][2*np+1], af[mt], &bf[np][2]);
        }
    }
    if(c+2<NC){
      int nb=buf+2; if(nb>=3) nb-=3;
      issue(c+2,nb);
    }
    if(++buf==3) buf=0;
  }

  // ---- epilogue ----
  #pragma unroll
  for(int mt=0;mt<2;mt++){
    int r0=m0+wm*32+mt*16+g4;
    #pragma unroll
    for(int half=0;half<2;half++){
      int r=r0+half*8;
      if(MODE==0){
        size_t ro=(size_t)(base+r)*ND;
        #pragma unroll
        for(int nt=0;nt<8;nt++){
          int col=n0+wn*64+nt*8+t4*2;
          float v0=acc[mt][nt][half*2+0]+bias[col+0];
          float v1=acc[mt][nt][half*2+1]+bias[col+1];
          __half2 hv=__floats2half2_rn(v0,v1);
          *(uint32_t*)(g_ada+ro+col)=*(uint32_t*)&hv;
        }
      } else if(MODE==1){
        size_t ro=(size_t)(base+r)*ND;
        #pragma unroll
        for(int nt=0;nt<8;nt++){
          int col=n0+wn*64+nt*8+t4*2;
          float v0=gelu_tanh(acc[mt][nt][half*2+0]+bias[col+0]);
          float v1=gelu_tanh(acc[mt][nt][half*2+1]+bias[col+1]);
          __half2 hv=__floats2half2_rn(v0,v1);
          *(uint32_t*)(g_u+ro+col)=*(uint32_t*)&hv;
        }
      } else {
        const __half* gp=g_ada+(size_t)(base+r)*AD3+2*D;
        float f; int tok;
        if(z<NE){
          int sidx=z*CAP+r;
          tok=g_slot_tok[sidx];
          if(tok<0) continue;
          f=g_slot_w[sidx]*p.mask[tok]*(2.f/3.f);
        } else {
          tok=r;
          f=p.mask[r]*(1.f/3.f);
        }
        float* op=p.out+(size_t)tok*D;
        #pragma unroll
        for(int nt=0;nt<8;nt++){
          int col=n0+wn*64+nt*8+t4*2;
          uint32_t gu=*(const uint32_t*)(gp+col);
          float2 gv=__half22float2(*(__half2*)&gu);
          atomicAdd(&op[col+0],(acc[mt][nt][half*2+0]+bias[col+0])*gv.x*f);
          atomicAdd(&op[col+1],(acc[mt][nt][half*2+1]+bias[col+1])*gv.y*f);
        }
      }
    }
  }
}

extern "C" void kernel_launch(void* const* d_in, const int* in_sizes, int n_in,
                              void* d_out, int out_size){
  P p;
  p.x     =(const float*)d_in[0];
  p.cond  =(const float*)d_in[1];
  p.mask  =(const float*)d_in[2];
  const float* Wg=(const float*)d_in[3];
  p.Wada_s=(const float*)d_in[4];
  p.bada_s=(const float*)d_in[5];
  p.W1_s  =(const float*)d_in[6];
  p.b1_s  =(const float*)d_in[7];
  p.W2_s  =(const float*)d_in[8];
  p.b2_s  =(const float*)d_in[9];
  p.Wada_e=(const float*)d_in[10];
  p.bada_e=(const float*)d_in[11];
  p.W1_e  =(const float*)d_in[12];
  p.b1_e  =(const float*)d_in[13];
  p.W2_e  =(const float*)d_in[14];
  p.b2_e  =(const float*)d_in[15];
  p.out   =(float*)d_out;

  const int SMEM_SZ=6*128*PADH*2;   // 110592 B
  cudaFuncSetAttribute(k_gemm_mma<0>, cudaFuncAttributeMaxDynamicSharedMemorySize, SMEM_SZ);
  cudaFuncSetAttribute(k_gemm_mma<1>, cudaFuncAttributeMaxDynamicSharedMemorySize, SMEM_SZ);
  cudaFuncSetAttribute(k_gemm_mma<2>, cudaFuncAttributeMaxDynamicSharedMemorySize, SMEM_SZ);

  void *pslot=nullptr, *pch=nullptr;
  cudaGetSymbolAddress(&pslot, g_slot_tok);
  cudaGetSymbolAddress(&pch,   g_condh);
  cudaMemsetAsync(pslot, 0xFF, sizeof(int)*ROWS_R, 0);
  cudaMemsetAsync(d_out, 0,    sizeof(float)*(size_t)T*D, 0);

  // fp16 cond; transpose+convert all weights to [N][K] fp16
  {
    size_t n4=(size_t)T*DCND/4;
    k_tohalf<<<(unsigned)((n4+255)/256),256>>>(p.cond,(__half*)pch,n4);
    dim3 b(32,8);
    dim3 ga(AD3/32, DCND/32, NE+1); k_wt<0><<<ga,b>>>(p);
    dim3 g1(HID/32, D/32,   NE+1);  k_wt<1><<<g1,b>>>(p);
    dim3 g2(D/32,   HID/32, NE+1);  k_wt<2><<<g2,b>>>(p);
  }

  k_router <<<T/4, 128>>>(p.x, Wg);
  k_hist   <<<NCHUNK, CHUNK>>>();
  k_scan   <<<1, 32>>>();
  k_place  <<<NCHUNK, CHUNK>>>();
  k_lnstats<<<T/4, 128>>>(p.x);

  dim3 g0(AD3/128, 64, NE+1);  k_gemm_mma<0><<<g0, 256, SMEM_SZ>>>(p);
  k_mod<<<ROWS_ALL, 256>>>(p.x);
  dim3 g1(HID/128, 64, NE+1);  k_gemm_mma<1><<<g1, 256, SMEM_SZ>>>(p);
  dim3 g2(D/128,   64, NE+1);  k_gemm_mma<2><<<g2, 256, SMEM_SZ>>>(p);
}

// round 9
// speedup vs baseline: 5.3059x; 1.0058x over previous
#include <cuda_runtime.h>
#include <cuda_fp16.h>
#include <math.h>
#include <stdint.h>

#define T 8192
#define D 1024
#define DCND 256
#define NE 8
#define HID 4096
#define CAP 2560
#define NTOK (T*2)
#define ROWS_R (NE*CAP)
#define ROWS_ALL (ROWS_R+T)
#define AD3 3072
#define NCHUNK 64
#define CHUNK 256
#define KC 64                 // K halves per chunk = 128B/row
#define PADH 72               // halves per smem row (64 + 8 pad) = 144B

// ---------------- scratch (device globals; no allocations) ----------------
__device__ int   g_tope[NTOK];
__device__ float g_topw[NTOK];
__device__ int   g_hist[NCHUNK*NE];
__device__ int   g_coff[NCHUNK*NE];
__device__ int   g_tpe[NE];
__device__ int   g_starts[NE];
__device__ int   g_ne[NE];
__device__ int   g_slot_tok[ROWS_R];
__device__ float g_slot_w[ROWS_R];
__device__ float g_mu[T];
__device__ float g_rstd[T];
__device__ __half g_gate[(size_t)ROWS_ALL*D];    // adaLN gate (fp16)
__device__ __half g_h[(size_t)ROWS_ALL*D];       // modulated LN input (fp16)
__device__ __half g_u[(size_t)ROWS_ALL*HID];     // gelu(h@W1+b1) (fp16)
__device__ __half g_condh[(size_t)T*DCND];       // fp16 cond
// transposed [z][N][K] fp16 weights (Wada column-permuted: pairs (shift_d,scale_d), then gate)
__device__ __half g_wadat[(size_t)(NE+1)*AD3*DCND];
__device__ __half g_w1t[(size_t)(NE+1)*HID*D];
__device__ __half g_w2t[(size_t)(NE+1)*D*HID];

struct P {
  const float *x,*cond,*mask;
  const float *Wada_s,*bada_s,*W1_s,*b1_s,*W2_s,*b2_s;
  const float *Wada_e,*bada_e,*W1_e,*b1_e,*W2_e,*b2_e;
  float *out;
};

// ---------------- helpers ----------------
__device__ __forceinline__ uint32_t s2u(const void* p){
  uint32_t a;
  asm("{ .reg .u64 t; cvta.to.shared.u64 t, %1; cvt.u32.u64 %0, t; }" : "=r"(a) : "l"(p));
  return a;
}
__device__ __forceinline__ void cp16(uint32_t d, const void* s, uint32_t sz){
  asm volatile("cp.async.cg.shared.global [%0], [%1], 16, %2;" :: "r"(d),"l"(s),"r"(sz) : "memory");
}
__device__ __forceinline__ void mma16(float* c, const uint32_t* a, const uint32_t* b){
  asm volatile("mma.sync.aligned.m16n8k16.row.col.f32.f16.f16.f32 "
    "{%0,%1,%2,%3}, {%4,%5,%6,%7}, {%8,%9}, {%0,%1,%2,%3};"
    : "+f"(c[0]),"+f"(c[1]),"+f"(c[2]),"+f"(c[3])
    : "r"(a[0]),"r"(a[1]),"r"(a[2]),"r"(a[3]), "r"(b[0]),"r"(b[1]));
}
__device__ __forceinline__ void ldsm4(uint32_t* r, uint32_t a){
  asm volatile("ldmatrix.sync.aligned.m8n8.x4.shared.b16 {%0,%1,%2,%3}, [%4];"
    : "=r"(r[0]),"=r"(r[1]),"=r"(r[2]),"=r"(r[3]) : "r"(a));
}

// ---------------- f32 -> f16 copy (cond) ----------------
__global__ void k_tohalf(const float* __restrict__ s, __half* __restrict__ d, size_t n4){
  size_t i=(size_t)blockIdx.x*blockDim.x+threadIdx.x;
  if(i>=n4) return;
  float4 v=((const float4*)s)[i];
  __half2 lo=__floats2half2_rn(v.x,v.y);
  __half2 hi=__floats2half2_rn(v.z,v.w);
  uint2 o; o.x=*(uint32_t*)&lo; o.y=*(uint32_t*)&hi;
  ((uint2*)d)[i]=o;
}

// ---------------- weight transpose [K,N]->[N,K] fp16 (MODE0: column-permuted) ----------------
template<int MODE>
__global__ void k_wt(P p){
  constexpr int KD=(MODE==0)?DCND:(MODE==1)?D:HID;
  constexpr int ND=(MODE==0)?AD3:(MODE==1)?HID:D;
  int z=blockIdx.z;
  const float* W;
  if(MODE==0) W=(z<NE)? p.Wada_e+(size_t)z*KD*ND : p.Wada_s;
  else if(MODE==1) W=(z<NE)? p.W1_e+(size_t)z*KD*ND : p.W1_s;
  else W=(z<NE)? p.W2_e+(size_t)z*KD*ND : p.W2_s;
  __half* Wt=((MODE==0)? g_wadat : (MODE==1)? g_w1t : g_w2t)+(size_t)z*KD*ND;
  __shared__ float t[32][33];
  int n0=blockIdx.x*32, k0=blockIdx.y*32;
  int tx=threadIdx.x, ty=threadIdx.y;
  int n=n0+tx;
  int srcn=n;
  if(MODE==0 && n<2*D) srcn=(n&1)? D+(n>>1) : (n>>1);   // interleave shift/scale
  #pragma unroll
  for(int i=0;i<32;i+=8)
    t[ty+i][tx]=W[(size_t)(k0+ty+i)*ND+srcn];
  __syncthreads();
  #pragma unroll
  for(int i=0;i<32;i+=8)
    Wt[(size_t)(n0+ty+i)*KD+k0+tx]=__float2half_rn(t[tx][ty+i]);
}

// ---------------- router + LN stats fused: warp/token ----------------
__global__ void k_router(const float* __restrict__ x, const float* __restrict__ Wg){
  int w=(blockIdx.x*blockDim.x+threadIdx.x)>>5;
  int lane=threadIdx.x&31;
  if(w>=T) return;
  const float* xr=x+(size_t)w*D;
  float a[7]={0.f,0.f,0.f,0.f,0.f,0.f,0.f};
  float s=0.f,s2=0.f;
  for(int k=lane;k<D;k+=32){
    float xv=xr[k];
    s+=xv; s2+=xv*xv;
    #pragma unroll
    for(int j=0;j<7;j++) a[j]+=xv*Wg[k*7+j];
  }
  #pragma unroll
  for(int j=0;j<7;j++)
    for(int o=16;o;o>>=1) a[j]+=__shfl_xor_sync(0xffffffffu,a[j],o);
  for(int o=16;o;o>>=1){
    s+=__shfl_xor_sync(0xffffffffu,s,o);
    s2+=__shfl_xor_sync(0xffffffffu,s2,o);
  }
  if(lane==0){
    int j0=0;
    #pragma unroll
    for(int j=1;j<7;j++) if(a[j]>a[j0]) j0=j;
    int j1=-1;
    #pragma unroll
    for(int j=0;j<7;j++){ if(j==j0) continue; if(j1<0||a[j]>a[j1]) j1=j; }
    float e1=expf(a[j1]-a[j0]);
    float inv=1.f/(1.f+e1);
    g_tope[2*w]=j0;   g_topw[2*w]=inv;
    g_tope[2*w+1]=j1; g_topw[2*w+1]=e1*inv;
    float mu=s*(1.f/(float)D);
    float var=s2*(1.f/(float)D)-mu*mu;
    g_mu[w]=mu;
    g_rstd[w]=rsqrtf(var+1e-5f);
  }
}

// ---------------- stable counting sort by expert ----------------
__global__ void k_hist(){
  __shared__ int cnt[NE];
  int tid=threadIdx.x;
  if(tid<NE) cnt[tid]=0;
  __syncthreads();
  atomicAdd(&cnt[g_tope[blockIdx.x*CHUNK+tid]],1);
  __syncthreads();
  if(tid<NE) g_hist[blockIdx.x*NE+tid]=cnt[tid];
}
__global__ void k_scan(){
  int tid=threadIdx.x;
  __shared__ int tpe[NE], st[NE];
  if(tid<NE){
    int s=0;
    for(int c=0;c<NCHUNK;c++) s+=g_hist[c*NE+tid];
    tpe[tid]=s; g_tpe[tid]=s; g_ne[tid]=s<CAP?s:CAP;
  }
  __syncthreads();
  if(tid==0){
    int cum=0;
    for(int e=0;e<NE;e++){ st[e]=cum; g_starts[e]=cum; cum+=tpe[e]; }
  }
  __syncthreads();
  if(tid<NE){
    int run=st[tid];
    for(int c=0;c<NCHUNK;c++){ g_coff[c*NE+tid]=run; run+=g_hist[c*NE+tid]; }
  }
}
__global__ void k_place(){
  __shared__ int se[CHUNK];
  int tid=threadIdx.x;
  int g=blockIdx.x*CHUNK+tid;
  int e=g_tope[g];
  se[tid]=e;
  __syncthreads();
  int rank=0;
  for(int j=0;j<tid;j++) rank += (se[j]==e);
  int pos=g_coff[blockIdx.x*NE+e]+rank;
  int slot=pos-g_starts[e];
  if(slot<CAP){
    g_slot_tok[e*CAP+slot]=g>>1;
    g_slot_w[e*CAP+slot]=g_topw[g];
  }
}

__device__ __forceinline__ float gelu_tanh(float v){
  const float c=0.7978845608028654f;
  return 0.5f*v*(1.f+tanhf(c*(v+0.044715f*v*v*v)));
}

// ---------------- fp16 mma.sync GEMM, 128x128 tile, 256 thr, 3-stage cp.async ----------------
// MODE 0: ada(permuted) = gather(condh) @ Wada' -> fused LN-modulate epilogue -> g_h, g_gate
// MODE 1: u   = f16(gelu(g_h @ W1 + b1))                (K=1024, N=4096)
// MODE 2: y   = g_u @ W2 + b2 -> gate*mask*w atomic out (K=4096, N=1024)
template<int MODE>
__global__ void __launch_bounds__(256,2) k_gemm_mma(P p){
  constexpr int KD=(MODE==0)?DCND:(MODE==1)?D:HID;
  constexpr int ND=(MODE==0)?AD3:(MODE==1)?HID:D;
  constexpr int NC=KD/KC;
  constexpr uint32_t BUF=128*PADH*2;    // 18432 B per stage per operand

  int z=blockIdx.z;
  int Mz=(z<NE)? g_ne[z] : T;
  int m0=blockIdx.y*128;
  if(m0>=Mz) return;
  int n0=blockIdx.x*128;
  int base=(z<NE)? z*CAP : ROWS_R;

  extern __shared__ __half smh[];
  uint32_t sa=s2u(smh);        // A: 3 stages
  uint32_t sb=sa+3*BUF;        // B: 3 stages

  int tid=threadIdx.x, warp=tid>>5, lane=tid&31;
  int wm=warp>>1, wn=warp&1;
  int g4=lane>>2, t4=lane&3;
  int tsel=lane>>3, tr=lane&7;

  const __half* Wt=((MODE==0)? g_wadat : (MODE==1)? g_w1t : g_w2t)+(size_t)z*(size_t)KD*ND;
  const float* bias;
  if(MODE==0) bias=(z<NE)? p.bada_e+z*AD3 : p.bada_s;
  else if(MODE==1) bias=(z<NE)? p.b1_e+z*HID : p.b1_s;
  else bias=(z<NE)? p.b2_e+z*D : p.b2_s;

  // loaders: thread owns row (tid>>1), half-row segment (tid&1)
  int lrow=tid>>1, lseg=tid&1;
  const __half* pA;
  uint32_t asz=16;
  if(MODE==0){
    int tok=(z<NE)? g_slot_tok[z*CAP+m0+lrow] : (m0+lrow);
    if(tok<0){ tok=0; asz=0; }
    pA=g_condh+(size_t)tok*DCND+lseg*32;
  } else {
    const __half* Ab=(MODE==1)? g_h : g_u;
    pA=Ab+(size_t)(base+m0+lrow)*KD+lseg*32;
  }
  const __half* pB=Wt+(size_t)(n0+lrow)*KD+lseg*32;

  uint32_t da0=sa+(uint32_t)(lrow*PADH+lseg*32)*2;
  uint32_t db0=sb+(uint32_t)(lrow*PADH+lseg*32)*2;

  uint32_t abase=sa+(uint32_t)(((wm*32+(tsel&1)*8+tr)*PADH+(tsel>>1)*8)*2);
  uint32_t bbase=sb+(uint32_t)(((wn*64+(tsel>>1)*8+tr)*PADH+(tsel&1)*8)*2);

  float acc[2][8][4];
  #pragma unroll
  for(int mt=0;mt<2;mt++)
    #pragma unroll
    for(int nt=0;nt<8;nt++)
      #pragma unroll
      for(int r=0;r<4;r++) acc[mt][nt][r]=0.f;

  auto issue=[&](int c,int buf){
    uint32_t da=da0+buf*BUF;
    const __half* srcA=pA+(size_t)c*KC;
    #pragma unroll
    for(int i=0;i<4;i++) cp16(da+i*16, srcA+i*8, asz);
    uint32_t db=db0+buf*BUF;
    const __half* srcB=pB+(size_t)c*KC;
    #pragma unroll
    for(int i=0;i<4;i++) cp16(db+i*16, srcB+i*8, 16u);
    asm volatile("cp.async.commit_group;" ::: "memory");
  };

  issue(0,0);
  if(NC>1) issue(1,1);
  int buf=0;
  for(int c=0;c<NC;c++){
    if(c+1<NC) asm volatile("cp.async.wait_group 1;" ::: "memory");
    else       asm volatile("cp.async.wait_group 0;" ::: "memory");
    __syncthreads();
    uint32_t ao=abase+buf*BUF;
    uint32_t bo=bbase+buf*BUF;
    #pragma unroll
    for(int kk=0;kk<4;kk++){                 // 4 x K16 per chunk
      uint32_t af[2][4], bf[4][4];
      #pragma unroll
      for(int mt=0;mt<2;mt++) ldsm4(af[mt], ao+(uint32_t)((mt*16*PADH)*2+kk*32));
      #pragma unroll
      for(int np=0;np<4;np++) ldsm4(bf[np], bo+(uint32_t)((np*16*PADH)*2+kk*32));
      #pragma unroll
      for(int mt=0;mt<2;mt++)
        #pragma unroll
        for(int np=0;np<4;np++){
          mma16(acc[mt][2*np+0], af[mt], &bf[np][0]);
          mma16(acc[mt][2*np+1], af[mt], &bf[np][2]);
        }
    }
    if(c+2<NC){
      int nb=buf+2; if(nb>=3) nb-=3;
      issue(c+2,nb);
    }
    if(++buf==3) buf=0;
  }

  // ---- epilogue ----
  #pragma unroll
  for(int mt=0;mt<2;mt++){
    int r0=m0+wm*32+mt*16+g4;
    #pragma unroll
    for(int half=0;half<2;half++){
      int r=r0+half*8;
      if(MODE==0){
        // fused LN-modulate: cols<2048 are (shift_d, scale_d) pairs; cols>=2048 gate
        int tok; bool valid=true;
        if(z<NE){ tok=g_slot_tok[z*CAP+r]; valid=(tok>=0); }
        else tok=r;
        float mu=0.f, rs=0.f;
        if(valid){ mu=g_mu[tok]; rs=g_rstd[tok]; }
        int strip=n0+wn*64;
        if(strip<2*D){
          __half* hp=g_h+(size_t)(base+r)*D;
          #pragma unroll
          for(int nt=0;nt<8;nt++){
            int d=(strip+nt*8+t4*2)>>1;
            float hv=0.f;
            if(valid){
              float sh=acc[mt][nt][half*2+0]+bias[d];
              float sc=acc[mt][nt][half*2+1]+bias[D+d];
              float xv=p.x[(size_t)tok*D+d];
              hv=(xv-mu)*rs*(1.f+sc)+sh;
            }
            hp[d]=__float2half_rn(hv);
          }
        } else {
          __half* gp=g_gate+(size_t)(base+r)*D;
          #pragma unroll
          for(int nt=0;nt<8;nt++){
            int d0=strip+nt*8+t4*2-2*D;
            float gv0=0.f, gv1=0.f;
            if(valid){
              gv0=acc[mt][nt][half*2+0]+bias[2*D+d0];
              gv1=acc[mt][nt][half*2+1]+bias[2*D+d0+1];
            }
            __half2 hv=__floats2half2_rn(gv0,gv1);
            *(uint32_t*)(gp+d0)=*(uint32_t*)&hv;
          }
        }
      } else if(MODE==1){
        size_t ro=(size_t)(base+r)*ND;
        #pragma unroll
        for(int nt=0;nt<8;nt++){
          int col=n0+wn*64+nt*8+t4*2;
          float v0=gelu_tanh(acc[mt][nt][half*2+0]+bias[col+0]);
          float v1=gelu_tanh(acc[mt][nt][half*2+1]+bias[col+1]);
          __half2 hv=__floats2half2_rn(v0,v1);
          *(uint32_t*)(g_u+ro+col)=*(uint32_t*)&hv;
        }
      } else {
        const __half* gp=g_gate+(size_t)(base+r)*D;
        float f; int tok;
        if(z<NE){
          int sidx=z*CAP+r;
          tok=g_slot_tok[sidx];
          if(tok<0) continue;
          f=g_slot_w[sidx]*p.mask[tok]*(2.f/3.f);
        } else {
          tok=r;
          f=p.mask[r]*(1.f/3.f);
        }
        float* op=p.out+(size_t)tok*D;
        #pragma unroll
        for(int nt=0;nt<8;nt++){
          int col=n0+wn*64+nt*8+t4*2;
          uint32_t gu=*(const uint32_t*)(gp+col);
          float2 gv=__half22float2(*(__half2*)&gu);
          atomicAdd(&op[col+0],(acc[mt][nt][half*2+0]+bias[col+0])*gv.x*f);
          atomicAdd(&op[col+1],(acc[mt][nt][half*2+1]+bias[col+1])*gv.y*f);
        }
      }
    }
  }
}

extern "C" void kernel_launch(void* const* d_in, const int* in_sizes, int n_in,
                              void* d_out, int out_size){
  P p;
  p.x     =(const float*)d_in[0];
  p.cond  =(const float*)d_in[1];
  p.mask  =(const float*)d_in[2];
  const float* Wg=(const float*)d_in[3];
  p.Wada_s=(const float*)d_in[4];
  p.bada_s=(const float*)d_in[5];
  p.W1_s  =(const float*)d_in[6];
  p.b1_s  =(const float*)d_in[7];
  p.W2_s  =(const float*)d_in[8];
  p.b2_s  =(const float*)d_in[9];
  p.Wada_e=(const float*)d_in[10];
  p.bada_e=(const float*)d_in[11];
  p.W1_e  =(const float*)d_in[12];
  p.b1_e  =(const float*)d_in[13];
  p.W2_e  =(const float*)d_in[14];
  p.b2_e  =(const float*)d_in[15];
  p.out   =(float*)d_out;

  const int SMEM_SZ=6*128*PADH*2;   // 110592 B
  cudaFuncSetAttribute(k_gemm_mma<0>, cudaFuncAttributeMaxDynamicSharedMemorySize, SMEM_SZ);
  cudaFuncSetAttribute(k_gemm_mma<1>, cudaFuncAttributeMaxDynamicSharedMemorySize, SMEM_SZ);
  cudaFuncSetAttribute(k_gemm_mma<2>, cudaFuncAttributeMaxDynamicSharedMemorySize, SMEM_SZ);

  void *pslot=nullptr, *pch=nullptr;
  cudaGetSymbolAddress(&pslot, g_slot_tok);
  cudaGetSymbolAddress(&pch,   g_condh);
  cudaMemsetAsync(pslot, 0xFF, sizeof(int)*ROWS_R, 0);
  cudaMemsetAsync(d_out, 0,    sizeof(float)*(size_t)T*D, 0);

  // fp16 cond; transpose+convert all weights to [N][K] fp16 (Wada permuted)
  {
    size_t n4=(size_t)T*DCND/4;
    k_tohalf<<<(unsigned)((n4+255)/256),256>>>(p.cond,(__half*)pch,n4);
    dim3 b(32,8);
    dim3 ga(AD3/32, DCND/32, NE+1); k_wt<0><<<ga,b>>>(p);
    dim3 g1(HID/32, D/32,   NE+1);  k_wt<1><<<g1,b>>>(p);
    dim3 g2(D/32,   HID/32, NE+1);  k_wt<2><<<g2,b>>>(p);
  }

  k_router <<<T/4, 128>>>(p.x, Wg);     // fused router + LN stats
  k_hist   <<<NCHUNK, CHUNK>>>();
  k_scan   <<<1, 32>>>();
  k_place  <<<NCHUNK, CHUNK>>>();

  dim3 g0(AD3/128, 64, NE+1);  k_gemm_mma<0><<<g0, 256, SMEM_SZ>>>(p);
  dim3 g1(HID/128, 64, NE+1);  k_gemm_mma<1><<<g1, 256, SMEM_SZ>>>(p);
  dim3 g2(D/128,   64, NE+1);  k_gemm_mma<2><<<g2, 256, SMEM_SZ>>>(p);
}

// round 10
// speedup vs baseline: 5.3257x; 1.0037x over previous
#include <cuda_runtime.h>
#include <cuda_fp16.h>
#include <math.h>
#include <stdint.h>

#define T 8192
#define D 1024
#define DCND 256
#define NE 8
#define HID 4096
#define CAP 2560
#define NTOK (T*2)
#define ROWS_R (NE*CAP)
#define ROWS_ALL (ROWS_R+T)
#define AD3 3072
#define NCHUNK 64
#define CHUNK 256
#define KC 64                 // K halves per chunk = 128B/row
#define PADH 72               // halves per smem row (64 + 8 pad) = 144B

// ---------------- scratch (device globals; no allocations) ----------------
__device__ int   g_tope[NTOK];
__device__ float g_topw[NTOK];
__device__ int   g_hist[NCHUNK*NE];
__device__ int   g_coff[NCHUNK*NE];
__device__ int   g_tpe[NE];
__device__ int   g_starts[NE];
__device__ int   g_ne[NE];
__device__ int   g_slot_tok[ROWS_R];
__device__ float g_slot_w[ROWS_R];
__device__ float g_mu[T];
__device__ float g_rstd[T];
__device__ __half g_gate[(size_t)ROWS_ALL*D];    // adaLN gate (fp16)
__device__ __half g_h[(size_t)ROWS_ALL*D];       // modulated LN input (fp16)
__device__ __half g_u[(size_t)ROWS_ALL*HID];     // gelu(h@W1+b1) (fp16)
__device__ __half g_condh[(size_t)T*DCND];       // fp16 cond
// transposed [z][N][K] fp16 weights (Wada column-permuted: pairs (shift_d,scale_d), then gate)
__device__ __half g_wadat[(size_t)(NE+1)*AD3*DCND];
__device__ __half g_w1t[(size_t)(NE+1)*HID*D];
__device__ __half g_w2t[(size_t)(NE+1)*D*HID];

struct P {
  const float *x,*cond,*mask;
  const float *Wada_s,*bada_s,*W1_s,*b1_s,*W2_s,*b2_s;
  const float *Wada_e,*bada_e,*W1_e,*b1_e,*W2_e,*b2_e;
  float *out;
};

// ---------------- helpers ----------------
__device__ __forceinline__ uint32_t s2u(const void* p){
  uint32_t a;
  asm("{ .reg .u64 t; cvta.to.shared.u64 t, %1; cvt.u32.u64 %0, t; }" : "=r"(a) : "l"(p));
  return a;
}
__device__ __forceinline__ void cp16(uint32_t d, const void* s, uint32_t sz){
  asm volatile("cp.async.cg.shared.global [%0], [%1], 16, %2;" :: "r"(d),"l"(s),"r"(sz) : "memory");
}
__device__ __forceinline__ void mma16(float* c, const uint32_t* a, const uint32_t* b){
  asm volatile("mma.sync.aligned.m16n8k16.row.col.f32.f16.f16.f32 "
    "{%0,%1,%2,%3}, {%4,%5,%6,%7}, {%8,%9}, {%0,%1,%2,%3};"
    : "+f"(c[0]),"+f"(c[1]),"+f"(c[2]),"+f"(c[3])
    : "r"(a[0]),"r"(a[1]),"r"(a[2]),"r"(a[3]), "r"(b[0]),"r"(b[1]));
}
__device__ __forceinline__ void ldsm4(uint32_t* r, uint32_t a){
  asm volatile("ldmatrix.sync.aligned.m8n8.x4.shared.b16 {%0,%1,%2,%3}, [%4];"
    : "=r"(r[0]),"=r"(r[1]),"=r"(r[2]),"=r"(r[3]) : "r"(a));
}

// ---------------- f32 -> f16 copy (cond) ----------------
__global__ void k_tohalf(const float* __restrict__ s, __half* __restrict__ d, size_t n4){
  size_t i=(size_t)blockIdx.x*blockDim.x+threadIdx.x;
  if(i>=n4) return;
  float4 v=((const float4*)s)[i];
  __half2 lo=__floats2half2_rn(v.x,v.y);
  __half2 hi=__floats2half2_rn(v.z,v.w);
  uint2 o; o.x=*(uint32_t*)&lo; o.y=*(uint32_t*)&hi;
  ((uint2*)d)[i]=o;
}

// ---------------- weight transpose [K,N]->[N,K] fp16 (MODE0: column-permuted) ----------------
template<int MODE>
__global__ void k_wt(P p){
  constexpr int KD=(MODE==0)?DCND:(MODE==1)?D:HID;
  constexpr int ND=(MODE==0)?AD3:(MODE==1)?HID:D;
  int z=blockIdx.z;
  const float* W;
  if(MODE==0) W=(z<NE)? p.Wada_e+(size_t)z*KD*ND : p.Wada_s;
  else if(MODE==1) W=(z<NE)? p.W1_e+(size_t)z*KD*ND : p.W1_s;
  else W=(z<NE)? p.W2_e+(size_t)z*KD*ND : p.W2_s;
  __half* Wt=((MODE==0)? g_wadat : (MODE==1)? g_w1t : g_w2t)+(size_t)z*KD*ND;
  __shared__ float t[32][33];
  int n0=blockIdx.x*32, k0=blockIdx.y*32;
  int tx=threadIdx.x, ty=threadIdx.y;
  int n=n0+tx;
  int srcn=n;
  if(MODE==0 && n<2*D) srcn=(n&1)? D+(n>>1) : (n>>1);   // interleave shift/scale
  #pragma unroll
  for(int i=0;i<32;i+=8)
    t[ty+i][tx]=W[(size_t)(k0+ty+i)*ND+srcn];
  __syncthreads();
  #pragma unroll
  for(int i=0;i<32;i+=8)
    Wt[(size_t)(n0+ty+i)*KD+k0+tx]=__float2half_rn(t[tx][ty+i]);
}

// ---------------- router + LN stats fused: warp/token ----------------
__global__ void k_router(const float* __restrict__ x, const float* __restrict__ Wg){
  int w=(blockIdx.x*blockDim.x+threadIdx.x)>>5;
  int lane=threadIdx.x&31;
  if(w>=T) return;
  const float* xr=x+(size_t)w*D;
  float a[7]={0.f,0.f,0.f,0.f,0.f,0.f,0.f};
  float s=0.f,s2=0.f;
  for(int k=lane;k<D;k+=32){
    float xv=xr[k];
    s+=xv; s2+=xv*xv;
    #pragma unroll
    for(int j=0;j<7;j++) a[j]+=xv*Wg[k*7+j];
  }
  #pragma unroll
  for(int j=0;j<7;j++)
    for(int o=16;o;o>>=1) a[j]+=__shfl_xor_sync(0xffffffffu,a[j],o);
  for(int o=16;o;o>>=1){
    s+=__shfl_xor_sync(0xffffffffu,s,o);
    s2+=__shfl_xor_sync(0xffffffffu,s2,o);
  }
  if(lane==0){
    int j0=0;
    #pragma unroll
    for(int j=1;j<7;j++) if(a[j]>a[j0]) j0=j;
    int j1=-1;
    #pragma unroll
    for(int j=0;j<7;j++){ if(j==j0) continue; if(j1<0||a[j]>a[j1]) j1=j; }
    float e1=expf(a[j1]-a[j0]);
    float inv=1.f/(1.f+e1);
    g_tope[2*w]=j0;   g_topw[2*w]=inv;
    g_tope[2*w+1]=j1; g_topw[2*w+1]=e1*inv;
    float mu=s*(1.f/(float)D);
    float var=s2*(1.f/(float)D)-mu*mu;
    g_mu[w]=mu;
    g_rstd[w]=rsqrtf(var+1e-5f);
  }
}

// ---------------- stable counting sort by expert ----------------
__global__ void k_hist(){
  __shared__ int cnt[NE];
  int tid=threadIdx.x;
  if(tid<NE) cnt[tid]=0;
  __syncthreads();
  atomicAdd(&cnt[g_tope[blockIdx.x*CHUNK+tid]],1);
  __syncthreads();
  if(tid<NE) g_hist[blockIdx.x*NE+tid]=cnt[tid];
}
__global__ void k_scan(){
  int tid=threadIdx.x;
  __shared__ int tpe[NE], st[NE];
  if(tid<NE){
    int s=0;
    for(int c=0;c<NCHUNK;c++) s+=g_hist[c*NE+tid];
    tpe[tid]=s; g_tpe[tid]=s; g_ne[tid]=s<CAP?s:CAP;
  }
  __syncthreads();
  if(tid==0){
    int cum=0;
    for(int e=0;e<NE;e++){ st[e]=cum; g_starts[e]=cum; cum+=tpe[e]; }
  }
  __syncthreads();
  if(tid<NE){
    int run=st[tid];
    for(int c=0;c<NCHUNK;c++){ g_coff[c*NE+tid]=run; run+=g_hist[c*NE+tid]; }
  }
}
__global__ void k_place(){
  __shared__ int se[CHUNK];
  int tid=threadIdx.x;
  int g=blockIdx.x*CHUNK+tid;
  int e=g_tope[g];
  se[tid]=e;
  __syncthreads();
  int rank=0;
  for(int j=0;j<tid;j++) rank += (se[j]==e);
  int pos=g_coff[blockIdx.x*NE+e]+rank;
  int slot=pos-g_starts[e];
  if(slot<CAP){
    g_slot_tok[e*CAP+slot]=g>>1;
    g_slot_w[e*CAP+slot]=g_topw[g];
  }
}

__device__ __forceinline__ float gelu_tanh(float v){
  const float c=0.7978845608028654f;
  return 0.5f*v*(1.f+tanhf(c*(v+0.044715f*v*v*v)));
}

// ---------------- fp16 mma.sync GEMM, 128x128 tile, 256 thr, 3-stage cp.async ----------------
// MODE 0: ada(permuted) = gather(condh) @ Wada' -> fused LN-modulate epilogue -> g_h, g_gate
// MODE 1: u   = f16(gelu(g_h @ W1 + b1))                (K=1024, N=4096)
// MODE 2: y   = g_u @ W2 + b2 -> gate*mask*w atomic out (K=4096, N=1024)
template<int MODE>
__global__ void __launch_bounds__(256,2) k_gemm_mma(P p){
  constexpr int KD=(MODE==0)?DCND:(MODE==1)?D:HID;
  constexpr int ND=(MODE==0)?AD3:(MODE==1)?HID:D;
  constexpr int NC=KD/KC;
  constexpr uint32_t BUF=128*PADH*2;    // 18432 B per stage per operand

  int z=blockIdx.z;
  int Mz=(z<NE)? g_ne[z] : T;
  int m0=blockIdx.y*128;
  if(m0>=Mz) return;
  int n0=blockIdx.x*128;
  int base=(z<NE)? z*CAP : ROWS_R;

  extern __shared__ __half smh[];
  uint32_t sa=s2u(smh);        // A: 3 stages
  uint32_t sb=sa+3*BUF;        // B: 3 stages

  int tid=threadIdx.x, warp=tid>>5, lane=tid&31;
  int wm=warp>>1, wn=warp&1;
  int g4=lane>>2, t4=lane&3;
  int tsel=lane>>3, tr=lane&7;

  const __half* Wt=((MODE==0)? g_wadat : (MODE==1)? g_w1t : g_w2t)+(size_t)z*(size_t)KD*ND;
  const float* bias;
  if(MODE==0) bias=(z<NE)? p.bada_e+z*AD3 : p.bada_s;
  else if(MODE==1) bias=(z<NE)? p.b1_e+z*HID : p.b1_s;
  else bias=(z<NE)? p.b2_e+z*D : p.b2_s;

  // loaders: thread owns row (tid>>1), half-row segment (tid&1)
  int lrow=tid>>1, lseg=tid&1;
  const __half* pA;
  uint32_t asz=16;
  if(MODE==0){
    int tok=(z<NE)? g_slot_tok[z*CAP+m0+lrow] : (m0+lrow);
    if(tok<0){ tok=0; asz=0; }
    pA=g_condh+(size_t)tok*DCND+lseg*32;
  } else {
    const __half* Ab=(MODE==1)? g_h : g_u;
    pA=Ab+(size_t)(base+m0+lrow)*KD+lseg*32;
  }
  const __half* pB=Wt+(size_t)(n0+lrow)*KD+lseg*32;

  uint32_t da0=sa+(uint32_t)(lrow*PADH+lseg*32)*2;
  uint32_t db0=sb+(uint32_t)(lrow*PADH+lseg*32)*2;

  uint32_t abase=sa+(uint32_t)(((wm*32+(tsel&1)*8+tr)*PADH+(tsel>>1)*8)*2);
  uint32_t bbase=sb+(uint32_t)(((wn*64+(tsel>>1)*8+tr)*PADH+(tsel&1)*8)*2);

  float acc[2][8][4];
  #pragma unroll
  for(int mt=0;mt<2;mt++)
    #pragma unroll
    for(int nt=0;nt<8;nt++)
      #pragma unroll
      for(int r=0;r<4;r++) acc[mt][nt][r]=0.f;

  auto issue=[&](int c,int buf){
    uint32_t da=da0+buf*BUF;
    const __half* srcA=pA+(size_t)c*KC;
    #pragma unroll
    for(int i=0;i<4;i++) cp16(da+i*16, srcA+i*8, asz);
    uint32_t db=db0+buf*BUF;
    const __half* srcB=pB+(size_t)c*KC;
    #pragma unroll
    for(int i=0;i<4;i++) cp16(db+i*16, srcB+i*8, 16u);
    asm volatile("cp.async.commit_group;" ::: "memory");
  };

  issue(0,0);
  if(NC>1) issue(1,1);
  int buf=0;
  for(int c=0;c<NC;c++){
    if(c+1<NC) asm volatile("cp.async.wait_group 1;" ::: "memory");
    else       asm volatile("cp.async.wait_group 0;" ::: "memory");
    __syncthreads();
    uint32_t ao=abase+buf*BUF;
    uint32_t bo=bbase+buf*BUF;
    #pragma unroll
    for(int kk=0;kk<4;kk++){                 // 4 x K16 per chunk
      uint32_t af[2][4], bf[4][4];
      #pragma unroll
      for(int mt=0;mt<2;mt++) ldsm4(af[mt], ao+(uint32_t)((mt*16*PADH)*2+kk*32));
      #pragma unroll
      for(int np=0;np<4;np++) ldsm4(bf[np], bo+(uint32_t)((np*16*PADH)*2+kk*32));
      #pragma unroll
      for(int mt=0;mt<2;mt++)
        #pragma unroll
        for(int np=0;np<4;np++){
          mma16(acc[mt][2*np+0], af[mt], &bf[np][0]);
          mma16(acc[mt][2*np+1], af[mt], &bf[np][2]);
        }
    }
    if(c+2<NC){
      int nb=buf+2; if(nb>=3) nb-=3;
      issue(c+2,nb);
    }
    if(++buf==3) buf=0;
  }

  // ---- epilogue ----
  #pragma unroll
  for(int mt=0;mt<2;mt++){
    int r0=m0+wm*32+mt*16+g4;
    #pragma unroll
    for(int half=0;half<2;half++){
      int r=r0+half*8;
      if(MODE==0){
        // fused LN-modulate: cols<2048 are (shift_d, scale_d) pairs; cols>=2048 gate
        int tok; bool valid=true;
        if(z<NE){ tok=g_slot_tok[z*CAP+r]; valid=(tok>=0); }
        else tok=r;
        float mu=0.f, rs=0.f;
        if(valid){ mu=g_mu[tok]; rs=g_rstd[tok]; }
        int strip=n0+wn*64;
        if(strip<2*D){
          __half* hp=g_h+(size_t)(base+r)*D;
          #pragma unroll
          for(int nt=0;nt<8;nt++){
            int d=(strip+nt*8+t4*2)>>1;
            float hv=0.f;
            if(valid){
              float sh=acc[mt][nt][half*2+0]+bias[d];
              float sc=acc[mt][nt][half*2+1]+bias[D+d];
              float xv=p.x[(size_t)tok*D+d];
              hv=(xv-mu)*rs*(1.f+sc)+sh;
            }
            hp[d]=__float2half_rn(hv);
          }
        } else {
          __half* gp=g_gate+(size_t)(base+r)*D;
          #pragma unroll
          for(int nt=0;nt<8;nt++){
            int d0=strip+nt*8+t4*2-2*D;
            float gv0=0.f, gv1=0.f;
            if(valid){
              gv0=acc[mt][nt][half*2+0]+bias[2*D+d0];
              gv1=acc[mt][nt][half*2+1]+bias[2*D+d0+1];
            }
            __half2 hv=__floats2half2_rn(gv0,gv1);
            *(uint32_t*)(gp+d0)=*(uint32_t*)&hv;
          }
        }
      } else if(MODE==1){
        size_t ro=(size_t)(base+r)*ND;
        #pragma unroll
        for(int nt=0;nt<8;nt++){
          int col=n0+wn*64+nt*8+t4*2;
          float v0=gelu_tanh(acc[mt][nt][half*2+0]+bias[col+0]);
          float v1=gelu_tanh(acc[mt][nt][half*2+1]+bias[col+1]);
          __half2 hv=__floats2half2_rn(v0,v1);
          *(uint32_t*)(g_u+ro+col)=*(uint32_t*)&hv;
        }
      } else {
        const __half* gp=g_gate+(size_t)(base+r)*D;
        float f; int tok;
        if(z<NE){
          int sidx=z*CAP+r;
          tok=g_slot_tok[sidx];
          if(tok<0) continue;
          f=g_slot_w[sidx]*p.mask[tok]*(2.f/3.f);
        } else {
          tok=r;
          f=p.mask[r]*(1.f/3.f);
        }
        float* op=p.out+(size_t)tok*D;
        #pragma unroll
        for(int nt=0;nt<8;nt++){
          int col=n0+wn*64+nt*8+t4*2;
          uint32_t gu=*(const uint32_t*)(gp+col);
          float2 gv=__half22float2(*(__half2*)&gu);
          atomicAdd(&op[col+0],(acc[mt][nt][half*2+0]+bias[col+0])*gv.x*f);
          atomicAdd(&op[col+1],(acc[mt][nt][half*2+1]+bias[col+1])*gv.y*f);
        }
      }
    }
  }
}

extern "C" void kernel_launch(void* const* d_in, const int* in_sizes, int n_in,
                              void* d_out, int out_size){
  P p;
  p.x     =(const float*)d_in[0];
  p.cond  =(const float*)d_in[1];
  p.mask  =(const float*)d_in[2];
  const float* Wg=(const float*)d_in[3];
  p.Wada_s=(const float*)d_in[4];
  p.bada_s=(const float*)d_in[5];
  p.W1_s  =(const float*)d_in[6];
  p.b1_s  =(const float*)d_in[7];
  p.W2_s  =(const float*)d_in[8];
  p.b2_s  =(const float*)d_in[9];
  p.Wada_e=(const float*)d_in[10];
  p.bada_e=(const float*)d_in[11];
  p.W1_e  =(const float*)d_in[12];
  p.b1_e  =(const float*)d_in[13];
  p.W2_e  =(const float*)d_in[14];
  p.b2_e  =(const float*)d_in[15];
  p.out   =(float*)d_out;

  const int SMEM_SZ=6*128*PADH*2;   // 110592 B
  cudaFuncSetAttribute(k_gemm_mma<0>, cudaFuncAttributeMaxDynamicSharedMemorySize, SMEM_SZ);
  cudaFuncSetAttribute(k_gemm_mma<1>, cudaFuncAttributeMaxDynamicSharedMemorySize, SMEM_SZ);
  cudaFuncSetAttribute(k_gemm_mma<2>, cudaFuncAttributeMaxDynamicSharedMemorySize, SMEM_SZ);

  // lazily-created side streams/events (host resources only; work is identical each call)
  static cudaStream_t sA=nullptr, sB=nullptr;
  static cudaEvent_t evFork=nullptr, ev1=nullptr, ev2=nullptr, evB=nullptr;
  if(!sA){
    cudaStreamCreateWithFlags(&sA, cudaStreamNonBlocking);
    cudaStreamCreateWithFlags(&sB, cudaStreamNonBlocking);
    cudaEventCreateWithFlags(&evFork, cudaEventDisableTiming);
    cudaEventCreateWithFlags(&ev1,    cudaEventDisableTiming);
    cudaEventCreateWithFlags(&ev2,    cudaEventDisableTiming);
    cudaEventCreateWithFlags(&evB,    cudaEventDisableTiming);
  }

  void *pslot=nullptr, *pch=nullptr;
  cudaGetSymbolAddress(&pslot, g_slot_tok);
  cudaGetSymbolAddress(&pch,   g_condh);

  // fork side streams off the origin (capture) stream
  cudaEventRecord(evFork, 0);
  cudaStreamWaitEvent(sA, evFork, 0);
  cudaStreamWaitEvent(sB, evFork, 0);

  // stream A: big weight transposes (consumed by MODE1 / MODE2)
  {
    dim3 b(32,8);
    dim3 g1(HID/32, D/32,   NE+1);  k_wt<1><<<g1,b,0,sA>>>(p);
    cudaEventRecord(ev1, sA);
    dim3 g2(D/32,   HID/32, NE+1);  k_wt<2><<<g2,b,0,sA>>>(p);
    cudaEventRecord(ev2, sA);
  }

  // stream B: routing chain (consumed by MODE0)
  {
    cudaMemsetAsync(pslot, 0xFF, sizeof(int)*ROWS_R, sB);
    k_router <<<T/4, 128, 0, sB>>>(p.x, Wg);     // fused router + LN stats
    k_hist   <<<NCHUNK, CHUNK, 0, sB>>>();
    k_scan   <<<1, 32, 0, sB>>>();
    k_place  <<<NCHUNK, CHUNK, 0, sB>>>();
    cudaEventRecord(evB, sB);
  }

  // origin stream: cond convert + Wada transpose + GEMM chain
  cudaMemsetAsync(d_out, 0, sizeof(float)*(size_t)T*D, 0);
  {
    size_t n4=(size_t)T*DCND/4;
    k_tohalf<<<(unsigned)((n4+255)/256),256>>>(p.cond,(__half*)pch,n4);
    dim3 b(32,8);
    dim3 ga(AD3/32, DCND/32, NE+1); k_wt<0><<<ga,b>>>(p);
  }
  cudaStreamWaitEvent(0, evB, 0);
  dim3 g0(AD3/128, 64, NE+1);  k_gemm_mma<0><<<g0, 256, SMEM_SZ>>>(p);
  cudaStreamWaitEvent(0, ev1, 0);
  dim3 g1(HID/128, 64, NE+1);  k_gemm_mma<1><<<g1, 256, SMEM_SZ>>>(p);
  cudaStreamWaitEvent(0, ev2, 0);
  dim3 g2(D/128,   64, NE+1);  k_gemm_mma<2><<<g2, 256, SMEM_SZ>>>(p);
}